// round 4
// baseline (speedup 1.0000x reference)
#include <cuda_runtime.h>
#include <cuda_bf16.h>
#include <math.h>
#include <float.h>
#include <stdint.h>

// ---------------- problem constants ----------------
#define BT   4096
#define KS   2048
#define KT   4096
#define VOC  32000
// ---------------- tiling ----------------
#define BM   128
#define BN   128
#define BK   64            // 128 bytes per row (bf16)
#define NT   250           // 32000/128 vocab tiles
#define NT4  1000          // NT * 4 warp_n slices
#define NPAD 1024
#define SCH  (KS/BK)       // 32 student chunks
#define NCH  (KS/BK + KT/BK)  // 96 chunks
#define NST  4
#define STAGE_B (BM*128 + BN*128)      // 32 KB
#define SMEM_BYTES (NST * STAGE_B)     // 128 KB

// ---------------- static device scratch ----------------
__device__ __nv_bfloat16 g_sin_bf[(size_t)BT * KS];
__device__ __nv_bfloat16 g_tin_bf[(size_t)BT * KT];
__device__ __nv_bfloat16 g_sw_bf [(size_t)VOC * KS];
__device__ __nv_bfloat16 g_tw_bf [(size_t)VOC * KT];

__device__ float g_m [(size_t)BT * NPAD];
__device__ float g_z [(size_t)BT * NPAD];
__device__ float g_d [(size_t)BT * NPAD];
__device__ float g_ss[(size_t)BT * NPAD];
__device__ float g_tt[(size_t)BT * NPAD];
__device__ float g_row[BT * 2];

// ---------------- PTX helpers ----------------
__device__ __forceinline__ uint32_t smem_u32(const void* p) {
    uint32_t a;
    asm("{ .reg .u64 t; cvta.to.shared.u64 t, %1; cvt.u32.u64 %0, t; }" : "=r"(a) : "l"(p));
    return a;
}
#define SWZ(o) ((o) ^ (((o) >> 3) & 0x70))

#define CP16(dst, src) \
    asm volatile("cp.async.cg.shared.global [%0], [%1], 16;" :: "r"(dst), "l"(src) : "memory")
#define CP_COMMIT() asm volatile("cp.async.commit_group;" ::: "memory")
#define CP_WAIT(n)  asm volatile("cp.async.wait_group %0;" :: "n"(n) : "memory")

#define LDSM4(r0, r1, r2, r3, a) \
    asm volatile("ldmatrix.sync.aligned.m8n8.x4.shared.b16 {%0,%1,%2,%3}, [%4];" \
        : "=r"(r0), "=r"(r1), "=r"(r2), "=r"(r3) : "r"(a))

#define MMA16816(d, a, b) \
    asm volatile("mma.sync.aligned.m16n8k16.row.col.f32.bf16.bf16.f32 " \
        "{%0,%1,%2,%3}, {%4,%5,%6,%7}, {%8,%9}, {%0,%1,%2,%3};" \
        : "+f"((d)[0]), "+f"((d)[1]), "+f"((d)[2]), "+f"((d)[3]) \
        : "r"((a)[0]), "r"((a)[1]), "r"((a)[2]), "r"((a)[3]), \
          "r"((b)[0]), "r"((b)[1]))

// ---------------- fused fp32 -> bf16 conversion (one launch, all 4 arrays) ----
#define N_SIN ((size_t)BT * KS)
#define N_TIN ((size_t)BT * KT)
#define N_SW  ((size_t)VOC * KS)
#define N_TW  ((size_t)VOC * KT)
#define N_TOT (N_SIN + N_TIN + N_SW + N_TW)

__global__ void cvt_all_kernel(const float* __restrict__ s_in,
                               const float* __restrict__ t_in,
                               const float* __restrict__ s_w,
                               const float* __restrict__ t_w) {
    size_t i = ((size_t)blockIdx.x * blockDim.x + threadIdx.x) * 4;
    size_t stride = (size_t)gridDim.x * blockDim.x * 4;
    for (; i < N_TOT; i += stride) {
        const float* src; __nv_bfloat16* dst; size_t off;
        if (i < N_SIN)                   { src = s_in; dst = g_sin_bf; off = i; }
        else if (i < N_SIN + N_TIN)      { src = t_in; dst = g_tin_bf; off = i - N_SIN; }
        else if (i < N_SIN + N_TIN + N_SW){ src = s_w; dst = g_sw_bf;  off = i - N_SIN - N_TIN; }
        else                             { src = t_w; dst = g_tw_bf;  off = i - N_SIN - N_TIN - N_SW; }
        float4 v = *reinterpret_cast<const float4*>(src + off);
        __nv_bfloat162 a = __float22bfloat162_rn(make_float2(v.x, v.y));
        __nv_bfloat162 b = __float22bfloat162_rn(make_float2(v.z, v.w));
        uint2 o;
        o.x = *reinterpret_cast<uint32_t*>(&a);
        o.y = *reinterpret_cast<uint32_t*>(&b);
        *reinterpret_cast<uint2*>(dst + off) = o;
    }
}

// ---------------- chunk loader (cp.async + SW128 swizzle) ----------------
__device__ __forceinline__ void load_chunk(int c, int st, uint32_t sb,
                                           int row0, int col0, int tid) {
    const __nv_bfloat16 *Ab, *Bb; int K, k0;
    if (c < SCH) { Ab = g_sin_bf; Bb = g_sw_bf; K = KS; k0 = c * BK; }
    else         { Ab = g_tin_bf; Bb = g_tw_bf; K = KT; k0 = (c - SCH) * BK; }
    uint32_t sA = sb + st * STAGE_B;
    uint32_t sB = sA + BM * 128;
#pragma unroll
    for (int i = 0; i < 4; i++) {              // A: 128 rows x 128B
        int ls = tid + i * 256;
        int row = ls >> 3, cb = (ls & 7) * 16;
        const char* g = (const char*)(Ab + (size_t)(row0 + row) * K + k0) + cb;
        CP16(sA + SWZ(ls * 16), g);
    }
#pragma unroll
    for (int i = 0; i < 4; i++) {              // B: 128 rows x 128B
        int ls = tid + i * 256;
        int row = ls >> 3, cb = (ls & 7) * 16;
        const char* g = (const char*)(Bb + (size_t)(col0 + row) * K + k0) + cb;
        CP16(sB + SWZ(ls * 16), g);
    }
}

// ---------------- one BK=64 chunk of MMAs ----------------
__device__ __forceinline__ void compute_chunk(float (&acc)[4][4][4],
                                              uint32_t sA, uint32_t sB,
                                              int wm, int wn, int lane) {
#pragma unroll
    for (int ks = 0; ks < 4; ks++) {
        uint32_t a[4][4];
#pragma unroll
        for (int mi = 0; mi < 4; mi++) {
            int row = wm * 64 + mi * 16 + (lane & 15);
            uint32_t off = row * 128 + ks * 32 + ((lane >> 4) << 4);
            LDSM4(a[mi][0], a[mi][1], a[mi][2], a[mi][3], sA + SWZ(off));
        }
        uint32_t b[4][2];
#pragma unroll
        for (int nj = 0; nj < 2; nj++) {
            int nrow = wn * 32 + nj * 16 + (lane & 7) + ((lane & 16) >> 1);
            uint32_t off = nrow * 128 + ks * 32 + (((lane >> 3) & 1) << 4);
            uint32_t r0, r1, r2, r3;
            LDSM4(r0, r1, r2, r3, sB + SWZ(off));
            b[2 * nj][0] = r0;     b[2 * nj][1] = r1;
            b[2 * nj + 1][0] = r2; b[2 * nj + 1][1] = r3;
        }
#pragma unroll
        for (int mi = 0; mi < 4; mi++)
#pragma unroll
            for (int ni = 0; ni < 4; ni++)
                MMA16816(acc[mi][ni], a[mi], b[ni]);
    }
}

// ---------------- main fused GEMM kernel ----------------
__global__ void __launch_bounds__(256, 1)
mma_fused_kernel() {
    extern __shared__ __align__(1024) char smem[];
    uint32_t sb = smem_u32(smem);
    const int tid = threadIdx.x, wid = tid >> 5, lane = tid & 31;
    const int wm = wid & 1, wn = wid >> 1;
    const int mt = blockIdx.x, nt = blockIdx.y;
    const int row0 = mt * BM, col0 = nt * BN;

    float accS[4][4][4], accT[4][4][4];
#pragma unroll
    for (int i = 0; i < 4; i++)
#pragma unroll
        for (int j = 0; j < 4; j++)
#pragma unroll
            for (int k = 0; k < 4; k++) { accS[i][j][k] = 0.f; accT[i][j][k] = 0.f; }

    // prologue: chunks 0,1,2 -> stages 0,1,2 (three groups in flight)
    load_chunk(0, 0, sb, row0, col0, tid); CP_COMMIT();
    load_chunk(1, 1, sb, row0, col0, tid); CP_COMMIT();
    load_chunk(2, 2, sb, row0, col0, tid); CP_COMMIT();

    for (int c = 0; c < NCH; c++) {
        const int st = c & (NST - 1);
        // outstanding groups before wait = min(NCH, c+3) - c; leave all but chunk c.
        if (c < NCH - 2)       CP_WAIT(2);
        else if (c == NCH - 2) CP_WAIT(1);
        else                   CP_WAIT(0);
        __syncthreads();   // chunk c visible to all; also orders compute(c-1) before
                           // the prefetch below overwriting stage (c+3)%4 == (c-1)%4

        const int p = c + 3;               // lag-3 prefetch
        if (p < NCH) {
            load_chunk(p, p & (NST - 1), sb, row0, col0, tid);
            CP_COMMIT();
        }

        uint32_t sA = sb + st * STAGE_B;
        uint32_t sB = sA + BM * 128;
        if (c < SCH) compute_chunk(accS, sA, sB, wm, wn, lane);
        else         compute_chunk(accT, sA, sB, wm, wn, lane);
    }

    // ---------------- epilogue: per-row partials over this warp's 32 cols ----
#pragma unroll
    for (int mi = 0; mi < 4; mi++) {
#pragma unroll
        for (int h = 0; h < 2; h++) {
            float s[8], t[8];
#pragma unroll
            for (int ni = 0; ni < 4; ni++) {
                s[2 * ni]     = accS[mi][ni][h * 2];
                s[2 * ni + 1] = accS[mi][ni][h * 2 + 1];
                t[2 * ni]     = accT[mi][ni][h * 2];
                t[2 * ni + 1] = accT[mi][ni][h * 2 + 1];
            }
            float m = s[0];
#pragma unroll
            for (int j = 1; j < 8; j++) m = fmaxf(m, s[j]);
            float z = 0.f, d = 0.f, ssq = 0.f, tsq = 0.f;
#pragma unroll
            for (int j = 0; j < 8; j++) {
                z += __expf(s[j] - m);
                d = fmaf(s[j], t[j], d);
                ssq = fmaf(s[j], s[j], ssq);
                tsq = fmaf(t[j], t[j], tsq);
            }
            // reduce across the 4 lanes sharing this row (quad)
#pragma unroll
            for (int off = 1; off < 4; off <<= 1) {
                float om = __shfl_xor_sync(0xffffffffu, m, off);
                float oz = __shfl_xor_sync(0xffffffffu, z, off);
                float od = __shfl_xor_sync(0xffffffffu, d, off);
                float os = __shfl_xor_sync(0xffffffffu, ssq, off);
                float ot = __shfl_xor_sync(0xffffffffu, tsq, off);
                float nm = fmaxf(m, om);
                z = z * __expf(m - nm) + oz * __expf(om - nm);
                m = nm;
                d += od; ssq += os; tsq += ot;
            }
            if ((lane & 3) == 0) {
                int row = row0 + wm * 64 + mi * 16 + h * 8 + (lane >> 2);
                size_t idx = (size_t)row * NPAD + nt * 4 + wn;
                g_m[idx] = m; g_z[idx] = z; g_d[idx] = d;
                g_ss[idx] = ssq; g_tt[idx] = tsq;
            }
        }
    }
}

// ---------------- K2: per-row combine + exact target logit ----------------
__global__ void combine_kernel(const int* __restrict__ tgt,
                               const float* __restrict__ s_in,
                               const float* __restrict__ s_w)
{
    int gw = (blockIdx.x * blockDim.x + threadIdx.x) >> 5;
    int lane = threadIdx.x & 31;
    if (gw >= BT) return;
    const int row = gw;

    float m = -FLT_MAX, z = 0.f, d = 0.f, ssq = 0.f, tsq = 0.f;
    for (int n = lane; n < NT4; n += 32) {
        size_t idx = (size_t)row * NPAD + n;
        float om = g_m[idx], oz = g_z[idx];
        float nm = fmaxf(m, om);
        z = z * __expf(m - nm) + oz * __expf(om - nm);
        m = nm;
        d += g_d[idx]; ssq += g_ss[idx]; tsq += g_tt[idx];
    }
#pragma unroll
    for (int off = 16; off > 0; off >>= 1) {
        float om = __shfl_xor_sync(0xffffffffu, m, off);
        float oz = __shfl_xor_sync(0xffffffffu, z, off);
        float od = __shfl_xor_sync(0xffffffffu, d, off);
        float os = __shfl_xor_sync(0xffffffffu, ssq, off);
        float ot = __shfl_xor_sync(0xffffffffu, tsq, off);
        float nm = fmaxf(m, om);
        z = z * __expf(m - nm) + oz * __expf(om - nm);
        m = nm;
        d += od; ssq += os; tsq += ot;
    }

    bool is64 = (tgt[1] == -1);            // int64 layout: high word of -100
    int t = is64 ? tgt[2 * row] : tgt[row];

    float ce = 0.f;
    if (t >= 0) {
        float p = 0.f;
        const float* a = s_in + (size_t)row * KS;
        const float* w = s_w + (size_t)t * KS;
        for (int k = lane * 4; k < KS; k += 128) {
            float4 va = *reinterpret_cast<const float4*>(&a[k]);
            float4 vw = *reinterpret_cast<const float4*>(&w[k]);
            p += va.x * vw.x + va.y * vw.y + va.z * vw.z + va.w * vw.w;
        }
#pragma unroll
        for (int off = 16; off > 0; off >>= 1)
            p += __shfl_xor_sync(0xffffffffu, p, off);
        ce = (m + __logf(z)) - p;
    }
    float cs = d / (fmaxf(sqrtf(ssq), 1e-12f) * fmaxf(sqrtf(tsq), 1e-12f));
    if (lane == 0) { g_row[2 * row] = ce; g_row[2 * row + 1] = cs; }
}

// ---------------- K3: final reduction ----------------
__global__ void finalize_kernel(float* __restrict__ out) {
    __shared__ float sce[256], scs[256];
    int tid = threadIdx.x;
    float ce = 0.f, cs = 0.f;
    for (int r = tid; r < BT; r += 256) {
        ce += g_row[2 * r];
        cs += 1.0f - g_row[2 * r + 1];
    }
    sce[tid] = ce; scs[tid] = cs;
    __syncthreads();
    for (int s = 128; s > 0; s >>= 1) {
        if (tid < s) { sce[tid] += sce[tid + s]; scs[tid] += scs[tid + s]; }
        __syncthreads();
    }
    if (tid == 0)
        out[0] = 0.5f * (sce[0] / (float)BT) + 0.25f * (scs[0] / (float)BT);
}

// ---------------- launch ----------------
extern "C" void kernel_launch(void* const* d_in, const int* in_sizes, int n_in,
                              void* d_out, int out_size)
{
    const float* s_in = (const float*)d_in[0];
    const float* t_in = (const float*)d_in[1];
    const float* s_w  = (const float*)d_in[2];
    const float* t_w  = (const float*)d_in[3];
    const int*   tgt  = (const int*)d_in[4];
    float* out = (float*)d_out;

    cudaFuncSetAttribute(mma_fused_kernel,
                         cudaFuncAttributeMaxDynamicSharedMemorySize, SMEM_BYTES);

    cvt_all_kernel<<<8192, 256>>>(s_in, t_in, s_w, t_w);

    dim3 grid(BT / BM, NT);   // mtile fast -> concurrent CTAs share weight tiles in L2
    mma_fused_kernel<<<grid, 256, SMEM_BYTES>>>();

    combine_kernel<<<(BT * 32) / 256, 256>>>(tgt, s_in, s_w);
    finalize_kernel<<<1, 256>>>(out);
}

// round 5
// speedup vs baseline: 1.7196x; 1.7196x over previous
#include <cuda_runtime.h>
#include <cuda_bf16.h>
#include <math.h>
#include <float.h>
#include <stdint.h>

// ---------------- problem constants ----------------
#define BT   4096
#define KS   2048
#define KT   4096
#define VOC  32000
// ---------------- tiling ----------------
#define BM   128
#define BN   128
#define BK   64            // 128 bytes per row (bf16)
#define NT   250           // 32000/128 vocab tiles
#define NT4  1000          // NT * 4 warp_n slices
#define NPAD 1024
#define SCH  (KS/BK)       // 32 student chunks
#define NCH  (KS/BK + KT/BK)  // 96 chunks
#define NST  3
#define STAGE_B (BM*128 + BN*128)      // 32 KB
#define SMEM_BYTES (NST * STAGE_B)     // 96 KB

// ---------------- static device scratch ----------------
__device__ __nv_bfloat16 g_sin_bf[(size_t)BT * KS];
__device__ __nv_bfloat16 g_tin_bf[(size_t)BT * KT];
__device__ __nv_bfloat16 g_sw_bf [(size_t)VOC * KS];
__device__ __nv_bfloat16 g_tw_bf [(size_t)VOC * KT];

__device__ float g_m [(size_t)BT * NPAD];
__device__ float g_z [(size_t)BT * NPAD];
__device__ float g_d [(size_t)BT * NPAD];
__device__ float g_ss[(size_t)BT * NPAD];
__device__ float g_tt[(size_t)BT * NPAD];
__device__ float g_row[BT * 2];

// ---------------- PTX helpers ----------------
__device__ __forceinline__ uint32_t smem_u32(const void* p) {
    uint32_t a;
    asm("{ .reg .u64 t; cvta.to.shared.u64 t, %1; cvt.u32.u64 %0, t; }" : "=r"(a) : "l"(p));
    return a;
}
#define SWZ(o) ((o) ^ (((o) >> 3) & 0x70))

#define CP16(dst, src) \
    asm volatile("cp.async.cg.shared.global [%0], [%1], 16;" :: "r"(dst), "l"(src) : "memory")
#define CP_COMMIT() asm volatile("cp.async.commit_group;" ::: "memory")
#define CP_WAIT(n)  asm volatile("cp.async.wait_group %0;" :: "n"(n) : "memory")

#define LDSM4(r0, r1, r2, r3, a) \
    asm volatile("ldmatrix.sync.aligned.m8n8.x4.shared.b16 {%0,%1,%2,%3}, [%4];" \
        : "=r"(r0), "=r"(r1), "=r"(r2), "=r"(r3) : "r"(a))

#define MMA16816(d, a, b) \
    asm volatile("mma.sync.aligned.m16n8k16.row.col.f32.bf16.bf16.f32 " \
        "{%0,%1,%2,%3}, {%4,%5,%6,%7}, {%8,%9}, {%0,%1,%2,%3};" \
        : "+f"((d)[0]), "+f"((d)[1]), "+f"((d)[2]), "+f"((d)[3]) \
        : "r"((a)[0]), "r"((a)[1]), "r"((a)[2]), "r"((a)[3]), \
          "r"((b)[0]), "r"((b)[1]))

// ---------------- fused fp32 -> bf16 conversion (one launch, all 4 arrays) ----
#define N_SIN ((size_t)BT * KS)
#define N_TIN ((size_t)BT * KT)
#define N_SW  ((size_t)VOC * KS)
#define N_TW  ((size_t)VOC * KT)
#define N_TOT (N_SIN + N_TIN + N_SW + N_TW)

__global__ void cvt_all_kernel(const float* __restrict__ s_in,
                               const float* __restrict__ t_in,
                               const float* __restrict__ s_w,
                               const float* __restrict__ t_w) {
    size_t i = ((size_t)blockIdx.x * blockDim.x + threadIdx.x) * 4;
    size_t stride = (size_t)gridDim.x * blockDim.x * 4;
    for (; i < N_TOT; i += stride) {
        const float* src; __nv_bfloat16* dst; size_t off;
        if (i < N_SIN)                    { src = s_in; dst = g_sin_bf; off = i; }
        else if (i < N_SIN + N_TIN)       { src = t_in; dst = g_tin_bf; off = i - N_SIN; }
        else if (i < N_SIN + N_TIN + N_SW){ src = s_w;  dst = g_sw_bf;  off = i - N_SIN - N_TIN; }
        else                              { src = t_w;  dst = g_tw_bf;  off = i - N_SIN - N_TIN - N_SW; }
        float4 v = *reinterpret_cast<const float4*>(src + off);
        __nv_bfloat162 a = __float22bfloat162_rn(make_float2(v.x, v.y));
        __nv_bfloat162 b = __float22bfloat162_rn(make_float2(v.z, v.w));
        uint2 o;
        o.x = *reinterpret_cast<uint32_t*>(&a);
        o.y = *reinterpret_cast<uint32_t*>(&b);
        *reinterpret_cast<uint2*>(dst + off) = o;
    }
}

// ---------------- chunk loader (cp.async + SW128 swizzle) ----------------
__device__ __forceinline__ void load_chunk(int c, int st, uint32_t sb,
                                           int row0, int col0, int tid) {
    const __nv_bfloat16 *Ab, *Bb; int K, k0;
    if (c < SCH) { Ab = g_sin_bf; Bb = g_sw_bf; K = KS; k0 = c * BK; }
    else         { Ab = g_tin_bf; Bb = g_tw_bf; K = KT; k0 = (c - SCH) * BK; }
    uint32_t sA = sb + st * STAGE_B;
    uint32_t sB = sA + BM * 128;
#pragma unroll
    for (int i = 0; i < 4; i++) {              // A: 128 rows x 128B
        int ls = tid + i * 256;
        int row = ls >> 3, cb = (ls & 7) * 16;
        const char* g = (const char*)(Ab + (size_t)(row0 + row) * K + k0) + cb;
        CP16(sA + SWZ(ls * 16), g);
    }
#pragma unroll
    for (int i = 0; i < 4; i++) {              // B: 128 rows x 128B
        int ls = tid + i * 256;
        int row = ls >> 3, cb = (ls & 7) * 16;
        const char* g = (const char*)(Bb + (size_t)(col0 + row) * K + k0) + cb;
        CP16(sB + SWZ(ls * 16), g);
    }
}

// ---------------- one BK=64 chunk of MMAs ----------------
__device__ __forceinline__ void compute_chunk(float (&acc)[4][4][4],
                                              uint32_t sA, uint32_t sB,
                                              int wm, int wn, int lane) {
#pragma unroll
    for (int ks = 0; ks < 4; ks++) {
        uint32_t a[4][4];
#pragma unroll
        for (int mi = 0; mi < 4; mi++) {
            int row = wm * 64 + mi * 16 + (lane & 15);
            uint32_t off = row * 128 + ks * 32 + ((lane >> 4) << 4);
            LDSM4(a[mi][0], a[mi][1], a[mi][2], a[mi][3], sA + SWZ(off));
        }
        uint32_t b[4][2];
#pragma unroll
        for (int nj = 0; nj < 2; nj++) {
            int nrow = wn * 32 + nj * 16 + (lane & 7) + ((lane & 16) >> 1);
            uint32_t off = nrow * 128 + ks * 32 + (((lane >> 3) & 1) << 4);
            uint32_t r0, r1, r2, r3;
            LDSM4(r0, r1, r2, r3, sB + SWZ(off));
            b[2 * nj][0] = r0;     b[2 * nj][1] = r1;
            b[2 * nj + 1][0] = r2; b[2 * nj + 1][1] = r3;
        }
#pragma unroll
        for (int mi = 0; mi < 4; mi++)
#pragma unroll
            for (int ni = 0; ni < 4; ni++)
                MMA16816(acc[mi][ni], a[mi], b[ni]);
    }
}

// ---------------- main fused GEMM kernel (round-3 proven structure) --------
__global__ void __launch_bounds__(256, 1)
mma_fused_kernel() {
    extern __shared__ __align__(1024) char smem[];
    uint32_t sb = smem_u32(smem);
    const int tid = threadIdx.x, wid = tid >> 5, lane = tid & 31;
    const int wm = wid & 1, wn = wid >> 1;
    const int mt = blockIdx.x, nt = blockIdx.y;
    const int row0 = mt * BM, col0 = nt * BN;

    float accS[4][4][4], accT[4][4][4];
#pragma unroll
    for (int i = 0; i < 4; i++)
#pragma unroll
        for (int j = 0; j < 4; j++)
#pragma unroll
            for (int k = 0; k < 4; k++) { accS[i][j][k] = 0.f; accT[i][j][k] = 0.f; }

    // prologue: chunks 0,1 -> stages 0,1
    load_chunk(0, 0, sb, row0, col0, tid); CP_COMMIT();
    load_chunk(1, 1, sb, row0, col0, tid); CP_COMMIT();

    for (int c = 0; c < NCH; c++) {
        const int st = c % NST;
        if (c + 1 < NCH) CP_WAIT(1); else CP_WAIT(0);
        __syncthreads();

        const int p = c + 2;
        if (p < NCH) {                 // stage (p%NST) was freed by iter c-1
            load_chunk(p, p % NST, sb, row0, col0, tid);
            CP_COMMIT();
        }

        uint32_t sA = sb + st * STAGE_B;
        uint32_t sB = sA + BM * 128;
        if (c < SCH) compute_chunk(accS, sA, sB, wm, wn, lane);
        else         compute_chunk(accT, sA, sB, wm, wn, lane);
        __syncthreads();               // compute done before stage reuse next iters
    }

    // ---------------- epilogue: per-row partials over this warp's 32 cols ----
#pragma unroll
    for (int mi = 0; mi < 4; mi++) {
#pragma unroll
        for (int h = 0; h < 2; h++) {
            float s[8], t[8];
#pragma unroll
            for (int ni = 0; ni < 4; ni++) {
                s[2 * ni]     = accS[mi][ni][h * 2];
                s[2 * ni + 1] = accS[mi][ni][h * 2 + 1];
                t[2 * ni]     = accT[mi][ni][h * 2];
                t[2 * ni + 1] = accT[mi][ni][h * 2 + 1];
            }
            float m = s[0];
#pragma unroll
            for (int j = 1; j < 8; j++) m = fmaxf(m, s[j]);
            float z = 0.f, d = 0.f, ssq = 0.f, tsq = 0.f;
#pragma unroll
            for (int j = 0; j < 8; j++) {
                z += __expf(s[j] - m);
                d = fmaf(s[j], t[j], d);
                ssq = fmaf(s[j], s[j], ssq);
                tsq = fmaf(t[j], t[j], tsq);
            }
            // reduce across the 4 lanes sharing this row (quad)
#pragma unroll
            for (int off = 1; off < 4; off <<= 1) {
                float om = __shfl_xor_sync(0xffffffffu, m, off);
                float oz = __shfl_xor_sync(0xffffffffu, z, off);
                float od = __shfl_xor_sync(0xffffffffu, d, off);
                float os = __shfl_xor_sync(0xffffffffu, ssq, off);
                float ot = __shfl_xor_sync(0xffffffffu, tsq, off);
                float nm = fmaxf(m, om);
                z = z * __expf(m - nm) + oz * __expf(om - nm);
                m = nm;
                d += od; ssq += os; tsq += ot;
            }
            if ((lane & 3) == 0) {
                int row = row0 + wm * 64 + mi * 16 + h * 8 + (lane >> 2);
                size_t idx = (size_t)row * NPAD + nt * 4 + wn;
                g_m[idx] = m; g_z[idx] = z; g_d[idx] = d;
                g_ss[idx] = ssq; g_tt[idx] = tsq;
            }
        }
    }
}

// ---------------- K2: per-row combine + exact target logit ----------------
__global__ void combine_kernel(const int* __restrict__ tgt,
                               const float* __restrict__ s_in,
                               const float* __restrict__ s_w)
{
    int gw = (blockIdx.x * blockDim.x + threadIdx.x) >> 5;
    int lane = threadIdx.x & 31;
    if (gw >= BT) return;
    const int row = gw;

    float m = -FLT_MAX, z = 0.f, d = 0.f, ssq = 0.f, tsq = 0.f;
    for (int n = lane; n < NT4; n += 32) {
        size_t idx = (size_t)row * NPAD + n;
        float om = g_m[idx], oz = g_z[idx];
        float nm = fmaxf(m, om);
        z = z * __expf(m - nm) + oz * __expf(om - nm);
        m = nm;
        d += g_d[idx]; ssq += g_ss[idx]; tsq += g_tt[idx];
    }
#pragma unroll
    for (int off = 16; off > 0; off >>= 1) {
        float om = __shfl_xor_sync(0xffffffffu, m, off);
        float oz = __shfl_xor_sync(0xffffffffu, z, off);
        float od = __shfl_xor_sync(0xffffffffu, d, off);
        float os = __shfl_xor_sync(0xffffffffu, ssq, off);
        float ot = __shfl_xor_sync(0xffffffffu, tsq, off);
        float nm = fmaxf(m, om);
        z = z * __expf(m - nm) + oz * __expf(om - nm);
        m = nm;
        d += od; ssq += os; tsq += ot;
    }

    bool is64 = (tgt[1] == -1);            // int64 layout: high word of -100
    int t = is64 ? tgt[2 * row] : tgt[row];

    float ce = 0.f;
    if (t >= 0) {
        float p = 0.f;
        const float* a = s_in + (size_t)row * KS;
        const float* w = s_w + (size_t)t * KS;
        for (int k = lane * 4; k < KS; k += 128) {
            float4 va = *reinterpret_cast<const float4*>(&a[k]);
            float4 vw = *reinterpret_cast<const float4*>(&w[k]);
            p += va.x * vw.x + va.y * vw.y + va.z * vw.z + va.w * vw.w;
        }
#pragma unroll
        for (int off = 16; off > 0; off >>= 1)
            p += __shfl_xor_sync(0xffffffffu, p, off);
        ce = (m + __logf(z)) - p;
    }
    float cs = d / (fmaxf(sqrtf(ssq), 1e-12f) * fmaxf(sqrtf(tsq), 1e-12f));
    if (lane == 0) { g_row[2 * row] = ce; g_row[2 * row + 1] = cs; }
}

// ---------------- K3: final reduction ----------------
__global__ void finalize_kernel(float* __restrict__ out) {
    __shared__ float sce[256], scs[256];
    int tid = threadIdx.x;
    float ce = 0.f, cs = 0.f;
    for (int r = tid; r < BT; r += 256) {
        ce += g_row[2 * r];
        cs += 1.0f - g_row[2 * r + 1];
    }
    sce[tid] = ce; scs[tid] = cs;
    __syncthreads();
    for (int s = 128; s > 0; s >>= 1) {
        if (tid < s) { sce[tid] += sce[tid + s]; scs[tid] += scs[tid + s]; }
        __syncthreads();
    }
    if (tid == 0)
        out[0] = 0.5f * (sce[0] / (float)BT) + 0.25f * (scs[0] / (float)BT);
}

// ---------------- launch ----------------
extern "C" void kernel_launch(void* const* d_in, const int* in_sizes, int n_in,
                              void* d_out, int out_size)
{
    const float* s_in = (const float*)d_in[0];
    const float* t_in = (const float*)d_in[1];
    const float* s_w  = (const float*)d_in[2];
    const float* t_w  = (const float*)d_in[3];
    const int*   tgt  = (const int*)d_in[4];
    float* out = (float*)d_out;

    cudaFuncSetAttribute(mma_fused_kernel,
                         cudaFuncAttributeMaxDynamicSharedMemorySize, SMEM_BYTES);

    cvt_all_kernel<<<8192, 256>>>(s_in, t_in, s_w, t_w);

    dim3 grid(BT / BM, NT);   // mtile fast -> concurrent CTAs share weight tiles in L2
    mma_fused_kernel<<<grid, 256, SMEM_BYTES>>>();

    combine_kernel<<<(BT * 32) / 256, 256>>>(tgt, s_in, s_w);
    finalize_kernel<<<1, 256>>>(out);
}

// round 6
// speedup vs baseline: 2.0680x; 1.2027x over previous
#include <cuda_runtime.h>
#include <cuda_bf16.h>
#include <math.h>
#include <float.h>
#include <stdint.h>

// ---------------- problem constants ----------------
#define BT   4096
#define KS   2048
#define KT   4096
#define VOC  32000
// ---------------- tiling ----------------
#define BM   128
#define BN   256
#define BK   64            // 128 bytes per row (bf16)
#define NT   125           // 32000/256 vocab tiles
#define NT4  500           // NT * 4 warp_n slices
#define NPAD 1024
#define NCH_S (KS/BK)      // 32
#define NCH_T (KT/BK)      // 64
#define NST  3
#define STAGE_B (BM*128 + BN*128)      // 48 KB
#define SMEM_BYTES (NST * STAGE_B)     // 144 KB
#define NCTA (32 * NT)                 // 4000

// ---------------- static device scratch ----------------
__device__ __nv_bfloat16 g_sin_bf[(size_t)BT * KS];
__device__ __nv_bfloat16 g_tin_bf[(size_t)BT * KT];
__device__ __nv_bfloat16 g_sw_bf [(size_t)VOC * KS];
__device__ __nv_bfloat16 g_tw_bf [(size_t)VOC * KT];

__device__ uint4 g_slog[(size_t)NCTA * 256 * 16];   // 262 MB: S fragments, reg-layout

__device__ float g_m [(size_t)BT * NPAD];
__device__ float g_z [(size_t)BT * NPAD];
__device__ float g_d [(size_t)BT * NPAD];
__device__ float g_ss[(size_t)BT * NPAD];
__device__ float g_tt[(size_t)BT * NPAD];
__device__ float g_row[BT * 2];

// ---------------- PTX helpers ----------------
__device__ __forceinline__ uint32_t smem_u32(const void* p) {
    uint32_t a;
    asm("{ .reg .u64 t; cvta.to.shared.u64 t, %1; cvt.u32.u64 %0, t; }" : "=r"(a) : "l"(p));
    return a;
}
#define SWZ(o) ((o) ^ (((o) >> 3) & 0x70))

#define CP16(dst, src) \
    asm volatile("cp.async.cg.shared.global [%0], [%1], 16;" :: "r"(dst), "l"(src) : "memory")
#define CP_COMMIT() asm volatile("cp.async.commit_group;" ::: "memory")
#define CP_WAIT(n)  asm volatile("cp.async.wait_group %0;" :: "n"(n) : "memory")

#define LDSM4(r0, r1, r2, r3, a) \
    asm volatile("ldmatrix.sync.aligned.m8n8.x4.shared.b16 {%0,%1,%2,%3}, [%4];" \
        : "=r"(r0), "=r"(r1), "=r"(r2), "=r"(r3) : "r"(a))

#define MMA16816(d, a, b) \
    asm volatile("mma.sync.aligned.m16n8k16.row.col.f32.bf16.bf16.f32 " \
        "{%0,%1,%2,%3}, {%4,%5,%6,%7}, {%8,%9}, {%0,%1,%2,%3};" \
        : "+f"((d)[0]), "+f"((d)[1]), "+f"((d)[2]), "+f"((d)[3]) \
        : "r"((a)[0]), "r"((a)[1]), "r"((a)[2]), "r"((a)[3]), \
          "r"((b)[0]), "r"((b)[1]))

// ---------------- fused fp32 -> bf16 conversion ----------------
#define N_SIN ((size_t)BT * KS)
#define N_TIN ((size_t)BT * KT)
#define N_SW  ((size_t)VOC * KS)
#define N_TW  ((size_t)VOC * KT)
#define N_TOT (N_SIN + N_TIN + N_SW + N_TW)

__global__ void cvt_all_kernel(const float* __restrict__ s_in,
                               const float* __restrict__ t_in,
                               const float* __restrict__ s_w,
                               const float* __restrict__ t_w) {
    size_t i = ((size_t)blockIdx.x * blockDim.x + threadIdx.x) * 4;
    size_t stride = (size_t)gridDim.x * blockDim.x * 4;
    for (; i < N_TOT; i += stride) {
        const float* src; __nv_bfloat16* dst; size_t off;
        if (i < N_SIN)                    { src = s_in; dst = g_sin_bf; off = i; }
        else if (i < N_SIN + N_TIN)       { src = t_in; dst = g_tin_bf; off = i - N_SIN; }
        else if (i < N_SIN + N_TIN + N_SW){ src = s_w;  dst = g_sw_bf;  off = i - N_SIN - N_TIN; }
        else                              { src = t_w;  dst = g_tw_bf;  off = i - N_SIN - N_TIN - N_SW; }
        float4 v = *reinterpret_cast<const float4*>(src + off);
        __nv_bfloat162 a = __float22bfloat162_rn(make_float2(v.x, v.y));
        __nv_bfloat162 b = __float22bfloat162_rn(make_float2(v.z, v.w));
        uint2 o;
        o.x = *reinterpret_cast<uint32_t*>(&a);
        o.y = *reinterpret_cast<uint32_t*>(&b);
        *reinterpret_cast<uint2*>(dst + off) = o;
    }
}

// ---------------- chunk loader: A 128 rows + B 256 rows of 128B ----------------
__device__ __forceinline__ void load_chunk(const __nv_bfloat16* __restrict__ Ab,
                                           const __nv_bfloat16* __restrict__ Bb,
                                           int K, int k0, int st, uint32_t sb,
                                           int row0, int col0, int tid) {
    uint32_t sA = sb + st * STAGE_B;
    uint32_t sB = sA + BM * 128;
#pragma unroll
    for (int i = 0; i < 4; i++) {
        int ls = tid + i * 256;
        int row = ls >> 3, cb = (ls & 7) * 16;
        const char* g = (const char*)(Ab + (size_t)(row0 + row) * K + k0) + cb;
        CP16(sA + SWZ(ls * 16), g);
    }
#pragma unroll
    for (int i = 0; i < 8; i++) {
        int ls = tid + i * 256;
        int row = ls >> 3, cb = (ls & 7) * 16;
        const char* g = (const char*)(Bb + (size_t)(col0 + row) * K + k0) + cb;
        CP16(sB + SWZ(ls * 16), g);
    }
}

// ---------------- one BK=64 chunk of MMAs: warp tile 64x64 ----------------
__device__ __forceinline__ void compute_chunk(float (&acc)[4][8][4],
                                              uint32_t sA, uint32_t sB,
                                              int wm, int wn, int lane) {
#pragma unroll
    for (int ks = 0; ks < 4; ks++) {
        uint32_t a[4][4];
#pragma unroll
        for (int mi = 0; mi < 4; mi++) {
            int row = wm * 64 + mi * 16 + (lane & 15);
            uint32_t off = row * 128 + ks * 32 + ((lane >> 4) << 4);
            LDSM4(a[mi][0], a[mi][1], a[mi][2], a[mi][3], sA + SWZ(off));
        }
        uint32_t b[8][2];
#pragma unroll
        for (int nj = 0; nj < 4; nj++) {
            int nrow = wn * 64 + nj * 16 + (lane & 7) + ((lane & 16) >> 1);
            uint32_t off = nrow * 128 + ks * 32 + (((lane >> 3) & 1) << 4);
            uint32_t r0, r1, r2, r3;
            LDSM4(r0, r1, r2, r3, sB + SWZ(off));
            b[2 * nj][0] = r0;     b[2 * nj][1] = r1;
            b[2 * nj + 1][0] = r2; b[2 * nj + 1][1] = r3;
        }
#pragma unroll
        for (int mi = 0; mi < 4; mi++)
#pragma unroll
            for (int ni = 0; ni < 8; ni++)
                MMA16816(acc[mi][ni], a[mi], b[ni]);
    }
}

// ---------------- shared mainloop (round-3 proven scheme) ----------------
__device__ __forceinline__ void gemm_mainloop(float (&acc)[4][8][4],
                                              const __nv_bfloat16* Ab,
                                              const __nv_bfloat16* Bb,
                                              int K, int nch, uint32_t sb,
                                              int row0, int col0,
                                              int tid, int wm, int wn, int lane) {
    load_chunk(Ab, Bb, K, 0,      0, sb, row0, col0, tid); CP_COMMIT();
    load_chunk(Ab, Bb, K, BK,     1, sb, row0, col0, tid); CP_COMMIT();

    for (int c = 0; c < nch; c++) {
        const int st = c % NST;
        if (c + 1 < nch) CP_WAIT(1); else CP_WAIT(0);
        __syncthreads();

        const int p = c + 2;
        if (p < nch) {
            load_chunk(Ab, Bb, K, p * BK, p % NST, sb, row0, col0, tid);
            CP_COMMIT();
        }
        uint32_t sA = sb + st * STAGE_B;
        uint32_t sB = sA + BM * 128;
        compute_chunk(acc, sA, sB, wm, wn, lane);
        __syncthreads();
    }
}

// ---------------- phase S: student GEMM ----------------
__global__ void __launch_bounds__(256, 1)
gemm_s_kernel() {
    extern __shared__ __align__(1024) char smem[];
    uint32_t sb = smem_u32(smem);
    const int tid = threadIdx.x, wid = tid >> 5, lane = tid & 31;
    const int wm = wid & 1, wn = wid >> 1;
    const int mt = blockIdx.x, nt = blockIdx.y;
    const int row0 = mt * BM, col0 = nt * BN;
    const int ctaLin = nt * 32 + mt;

    float acc[4][8][4];
#pragma unroll
    for (int i = 0; i < 4; i++)
#pragma unroll
        for (int j = 0; j < 8; j++)
#pragma unroll
            for (int k = 0; k < 4; k++) acc[i][j][k] = 0.f;

    gemm_mainloop(acc, g_sin_bf, g_sw_bf, KS, NCH_S, sb, row0, col0, tid, wm, wn, lane);

    // ---- store S fragments to scratch (reg-layout, coalesced uint4) ----
    {
        size_t base = (size_t)ctaLin * 4096 + tid;   // uint4 units, stride 256
#pragma unroll
        for (int mi = 0; mi < 4; mi++) {
#pragma unroll
            for (int nj = 0; nj < 4; nj++) {         // two ni per uint4
                uint32_t u[4];
#pragma unroll
                for (int q = 0; q < 2; q++) {
                    int ni = nj * 2 + q;
                    __nv_bfloat162 p0 = __float22bfloat162_rn(
                        make_float2(acc[mi][ni][0], acc[mi][ni][1]));
                    __nv_bfloat162 p1 = __float22bfloat162_rn(
                        make_float2(acc[mi][ni][2], acc[mi][ni][3]));
                    u[2 * q]     = *reinterpret_cast<uint32_t*>(&p0);
                    u[2 * q + 1] = *reinterpret_cast<uint32_t*>(&p1);
                }
                g_slog[base + (size_t)(mi * 4 + nj) * 256] =
                    make_uint4(u[0], u[1], u[2], u[3]);
            }
        }
    }

    // ---- per-row partials (m, z, ssq) over this warp's 64 cols ----
#pragma unroll
    for (int mi = 0; mi < 4; mi++) {
#pragma unroll
        for (int h = 0; h < 2; h++) {
            float s[16];
#pragma unroll
            for (int ni = 0; ni < 8; ni++) {
                s[2 * ni]     = acc[mi][ni][h * 2];
                s[2 * ni + 1] = acc[mi][ni][h * 2 + 1];
            }
            float m = s[0];
#pragma unroll
            for (int j = 1; j < 16; j++) m = fmaxf(m, s[j]);
            float z = 0.f, ssq = 0.f;
#pragma unroll
            for (int j = 0; j < 16; j++) {
                z += __expf(s[j] - m);
                ssq = fmaf(s[j], s[j], ssq);
            }
#pragma unroll
            for (int off = 1; off < 4; off <<= 1) {
                float om = __shfl_xor_sync(0xffffffffu, m, off);
                float oz = __shfl_xor_sync(0xffffffffu, z, off);
                float os = __shfl_xor_sync(0xffffffffu, ssq, off);
                float nm = fmaxf(m, om);
                z = z * __expf(m - nm) + oz * __expf(om - nm);
                m = nm;
                ssq += os;
            }
            if ((lane & 3) == 0) {
                int row = row0 + wm * 64 + mi * 16 + h * 8 + (lane >> 2);
                size_t idx = (size_t)row * NPAD + nt * 4 + wn;
                g_m[idx] = m; g_z[idx] = z; g_ss[idx] = ssq;
            }
        }
    }
}

// ---------------- phase T: teacher GEMM + dot/tsq ----------------
__global__ void __launch_bounds__(256, 1)
gemm_t_kernel() {
    extern __shared__ __align__(1024) char smem[];
    uint32_t sb = smem_u32(smem);
    const int tid = threadIdx.x, wid = tid >> 5, lane = tid & 31;
    const int wm = wid & 1, wn = wid >> 1;
    const int mt = blockIdx.x, nt = blockIdx.y;
    const int row0 = mt * BM, col0 = nt * BN;
    const int ctaLin = nt * 32 + mt;

    float acc[4][8][4];
#pragma unroll
    for (int i = 0; i < 4; i++)
#pragma unroll
        for (int j = 0; j < 8; j++)
#pragma unroll
            for (int k = 0; k < 4; k++) acc[i][j][k] = 0.f;

    gemm_mainloop(acc, g_tin_bf, g_tw_bf, KT, NCH_T, sb, row0, col0, tid, wm, wn, lane);

    // ---- dot / tsq against reloaded S fragments ----
    size_t base = (size_t)ctaLin * 4096 + tid;
#pragma unroll
    for (int mi = 0; mi < 4; mi++) {
        uint32_t su[16];
#pragma unroll
        for (int nj = 0; nj < 4; nj++) {
            uint4 v = g_slog[base + (size_t)(mi * 4 + nj) * 256];
            su[4 * nj] = v.x; su[4 * nj + 1] = v.y;
            su[4 * nj + 2] = v.z; su[4 * nj + 3] = v.w;
        }
#pragma unroll
        for (int h = 0; h < 2; h++) {
            float d = 0.f, tsq = 0.f;
#pragma unroll
            for (int ni = 0; ni < 8; ni++) {
                uint32_t u = su[ni * 2 + h];          // regs (2h, 2h+1) of (mi,ni)
                float s0 = __uint_as_float(u << 16);
                float s1 = __uint_as_float(u & 0xffff0000u);
                float t0 = acc[mi][ni][h * 2];
                float t1 = acc[mi][ni][h * 2 + 1];
                d = fmaf(s0, t0, d); d = fmaf(s1, t1, d);
                tsq = fmaf(t0, t0, tsq); tsq = fmaf(t1, t1, tsq);
            }
#pragma unroll
            for (int off = 1; off < 4; off <<= 1) {
                d   += __shfl_xor_sync(0xffffffffu, d, off);
                tsq += __shfl_xor_sync(0xffffffffu, tsq, off);
            }
            if ((lane & 3) == 0) {
                int row = row0 + wm * 64 + mi * 16 + h * 8 + (lane >> 2);
                size_t idx = (size_t)row * NPAD + nt * 4 + wn;
                g_d[idx] = d; g_tt[idx] = tsq;
            }
        }
    }
}

// ---------------- K2: per-row combine + exact target logit ----------------
__global__ void combine_kernel(const int* __restrict__ tgt,
                               const float* __restrict__ s_in,
                               const float* __restrict__ s_w)
{
    int gw = (blockIdx.x * blockDim.x + threadIdx.x) >> 5;
    int lane = threadIdx.x & 31;
    if (gw >= BT) return;
    const int row = gw;

    float m = -FLT_MAX, z = 0.f, d = 0.f, ssq = 0.f, tsq = 0.f;
    for (int n = lane; n < NT4; n += 32) {
        size_t idx = (size_t)row * NPAD + n;
        float om = g_m[idx], oz = g_z[idx];
        float nm = fmaxf(m, om);
        z = z * __expf(m - nm) + oz * __expf(om - nm);
        m = nm;
        d += g_d[idx]; ssq += g_ss[idx]; tsq += g_tt[idx];
    }
#pragma unroll
    for (int off = 16; off > 0; off >>= 1) {
        float om = __shfl_xor_sync(0xffffffffu, m, off);
        float oz = __shfl_xor_sync(0xffffffffu, z, off);
        float od = __shfl_xor_sync(0xffffffffu, d, off);
        float os = __shfl_xor_sync(0xffffffffu, ssq, off);
        float ot = __shfl_xor_sync(0xffffffffu, tsq, off);
        float nm = fmaxf(m, om);
        z = z * __expf(m - nm) + oz * __expf(om - nm);
        m = nm;
        d += od; ssq += os; tsq += ot;
    }

    bool is64 = (tgt[1] == -1);            // int64 layout: high word of -100
    int t = is64 ? tgt[2 * row] : tgt[row];

    float ce = 0.f;
    if (t >= 0) {
        float p = 0.f;
        const float* a = s_in + (size_t)row * KS;
        const float* w = s_w + (size_t)t * KS;
        for (int k = lane * 4; k < KS; k += 128) {
            float4 va = *reinterpret_cast<const float4*>(&a[k]);
            float4 vw = *reinterpret_cast<const float4*>(&w[k]);
            p += va.x * vw.x + va.y * vw.y + va.z * vw.z + va.w * vw.w;
        }
#pragma unroll
        for (int off = 16; off > 0; off >>= 1)
            p += __shfl_xor_sync(0xffffffffu, p, off);
        ce = (m + __logf(z)) - p;
    }
    float cs = d / (fmaxf(sqrtf(ssq), 1e-12f) * fmaxf(sqrtf(tsq), 1e-12f));
    if (lane == 0) { g_row[2 * row] = ce; g_row[2 * row + 1] = cs; }
}

// ---------------- K3: final reduction ----------------
__global__ void finalize_kernel(float* __restrict__ out) {
    __shared__ float sce[256], scs[256];
    int tid = threadIdx.x;
    float ce = 0.f, cs = 0.f;
    for (int r = tid; r < BT; r += 256) {
        ce += g_row[2 * r];
        cs += 1.0f - g_row[2 * r + 1];
    }
    sce[tid] = ce; scs[tid] = cs;
    __syncthreads();
    for (int s = 128; s > 0; s >>= 1) {
        if (tid < s) { sce[tid] += sce[tid + s]; scs[tid] += scs[tid + s]; }
        __syncthreads();
    }
    if (tid == 0)
        out[0] = 0.5f * (sce[0] / (float)BT) + 0.25f * (scs[0] / (float)BT);
}

// ---------------- launch ----------------
extern "C" void kernel_launch(void* const* d_in, const int* in_sizes, int n_in,
                              void* d_out, int out_size)
{
    const float* s_in = (const float*)d_in[0];
    const float* t_in = (const float*)d_in[1];
    const float* s_w  = (const float*)d_in[2];
    const float* t_w  = (const float*)d_in[3];
    const int*   tgt  = (const int*)d_in[4];
    float* out = (float*)d_out;

    cudaFuncSetAttribute(gemm_s_kernel,
                         cudaFuncAttributeMaxDynamicSharedMemorySize, SMEM_BYTES);
    cudaFuncSetAttribute(gemm_t_kernel,
                         cudaFuncAttributeMaxDynamicSharedMemorySize, SMEM_BYTES);

    cvt_all_kernel<<<8192, 256>>>(s_in, t_in, s_w, t_w);

    dim3 grid(BT / BM, NT);
    gemm_s_kernel<<<grid, 256, SMEM_BYTES>>>();
    gemm_t_kernel<<<grid, 256, SMEM_BYTES>>>();

    combine_kernel<<<(BT * 32) / 256, 256>>>(tgt, s_in, s_w);
    finalize_kernel<<<1, 256>>>(out);
}

// round 7
// speedup vs baseline: 2.1008x; 1.0159x over previous
#include <cuda_runtime.h>
#include <cuda_bf16.h>
#include <math.h>
#include <float.h>
#include <stdint.h>

// ---------------- problem constants ----------------
#define BT   4096
#define KS   2048
#define KT   4096
#define VOC  32000
// ---------------- tiling ----------------
#define BM   128
#define BN   256
#define BK   64            // 128 bytes per row (bf16)
#define NT   125           // 32000/256 vocab tiles
#define NT4  500           // NT * 4 warp_n slices
#define NPAD 1024
#define NCH_S (KS/BK)      // 32
#define NCH_T (KT/BK)      // 64
#define NST  3
#define STAGE_B (BM*128 + BN*128)      // 48 KB
#define SMEM_BYTES (NST * STAGE_B)     // 144 KB
#define NCTA (32 * NT)                 // 4000

// ---------------- static device scratch ----------------
__device__ __nv_bfloat16 g_sin_bf[(size_t)BT * KS];
__device__ __nv_bfloat16 g_tin_bf[(size_t)BT * KT];
__device__ __nv_bfloat16 g_sw_bf [(size_t)VOC * KS];
__device__ __nv_bfloat16 g_tw_bf [(size_t)VOC * KT];

__device__ uint4 g_slog[(size_t)NCTA * 256 * 16];   // 262 MB: S fragments, reg-layout

__device__ float g_m [(size_t)BT * NPAD];
__device__ float g_z [(size_t)BT * NPAD];
__device__ float g_d [(size_t)BT * NPAD];
__device__ float g_ss[(size_t)BT * NPAD];
__device__ float g_tt[(size_t)BT * NPAD];
__device__ float g_row[BT * 2];

// ---------------- PTX helpers ----------------
__device__ __forceinline__ uint32_t smem_u32(const void* p) {
    uint32_t a;
    asm("{ .reg .u64 t; cvta.to.shared.u64 t, %1; cvt.u32.u64 %0, t; }" : "=r"(a) : "l"(p));
    return a;
}
#define SWZ(o) ((o) ^ (((o) >> 3) & 0x70))

#define CP16(dst, src) \
    asm volatile("cp.async.cg.shared.global [%0], [%1], 16;" :: "r"(dst), "l"(src) : "memory")
#define CP_COMMIT() asm volatile("cp.async.commit_group;" ::: "memory")
#define CP_WAIT(n)  asm volatile("cp.async.wait_group %0;" :: "n"(n) : "memory")

#define LDSM4(r0, r1, r2, r3, a) \
    asm volatile("ldmatrix.sync.aligned.m8n8.x4.shared.b16 {%0,%1,%2,%3}, [%4];" \
        : "=r"(r0), "=r"(r1), "=r"(r2), "=r"(r3) : "r"(a))

#define MMA16816(d, a, b) \
    asm volatile("mma.sync.aligned.m16n8k16.row.col.f32.bf16.bf16.f32 " \
        "{%0,%1,%2,%3}, {%4,%5,%6,%7}, {%8,%9}, {%0,%1,%2,%3};" \
        : "+f"((d)[0]), "+f"((d)[1]), "+f"((d)[2]), "+f"((d)[3]) \
        : "r"((a)[0]), "r"((a)[1]), "r"((a)[2]), "r"((a)[3]), \
          "r"((b)[0]), "r"((b)[1]))

// ---------------- fused fp32 -> bf16 conversion ----------------
#define N_SIN ((size_t)BT * KS)
#define N_TIN ((size_t)BT * KT)
#define N_SW  ((size_t)VOC * KS)
#define N_TW  ((size_t)VOC * KT)
#define N_TOT (N_SIN + N_TIN + N_SW + N_TW)

__global__ void cvt_all_kernel(const float* __restrict__ s_in,
                               const float* __restrict__ t_in,
                               const float* __restrict__ s_w,
                               const float* __restrict__ t_w) {
    size_t i = ((size_t)blockIdx.x * blockDim.x + threadIdx.x) * 4;
    size_t stride = (size_t)gridDim.x * blockDim.x * 4;
    for (; i < N_TOT; i += stride) {
        const float* src; __nv_bfloat16* dst; size_t off;
        if (i < N_SIN)                    { src = s_in; dst = g_sin_bf; off = i; }
        else if (i < N_SIN + N_TIN)       { src = t_in; dst = g_tin_bf; off = i - N_SIN; }
        else if (i < N_SIN + N_TIN + N_SW){ src = s_w;  dst = g_sw_bf;  off = i - N_SIN - N_TIN; }
        else                              { src = t_w;  dst = g_tw_bf;  off = i - N_SIN - N_TIN - N_SW; }
        float4 v = *reinterpret_cast<const float4*>(src + off);
        __nv_bfloat162 a = __float22bfloat162_rn(make_float2(v.x, v.y));
        __nv_bfloat162 b = __float22bfloat162_rn(make_float2(v.z, v.w));
        uint2 o;
        o.x = *reinterpret_cast<uint32_t*>(&a);
        o.y = *reinterpret_cast<uint32_t*>(&b);
        *reinterpret_cast<uint2*>(dst + off) = o;
    }
}

// ---------------- chunk loader: A 128 rows + B 256 rows of 128B ----------------
__device__ __forceinline__ void load_chunk(const __nv_bfloat16* __restrict__ Ab,
                                           const __nv_bfloat16* __restrict__ Bb,
                                           int K, int k0, int st, uint32_t sb,
                                           int row0, int col0, int tid) {
    uint32_t sA = sb + st * STAGE_B;
    uint32_t sB = sA + BM * 128;
#pragma unroll
    for (int i = 0; i < 4; i++) {
        int ls = tid + i * 256;
        int row = ls >> 3, cb = (ls & 7) * 16;
        const char* g = (const char*)(Ab + (size_t)(row0 + row) * K + k0) + cb;
        CP16(sA + SWZ(ls * 16), g);
    }
#pragma unroll
    for (int i = 0; i < 8; i++) {
        int ls = tid + i * 256;
        int row = ls >> 3, cb = (ls & 7) * 16;
        const char* g = (const char*)(Bb + (size_t)(col0 + row) * K + k0) + cb;
        CP16(sB + SWZ(ls * 16), g);
    }
}

// ---------------- one BK=64 chunk of MMAs: warp tile 64x64 ----------------
__device__ __forceinline__ void compute_chunk(float (&acc)[4][8][4],
                                              uint32_t sA, uint32_t sB,
                                              int wm, int wn, int lane) {
#pragma unroll
    for (int ks = 0; ks < 4; ks++) {
        uint32_t a[4][4];
#pragma unroll
        for (int mi = 0; mi < 4; mi++) {
            int row = wm * 64 + mi * 16 + (lane & 15);
            uint32_t off = row * 128 + ks * 32 + ((lane >> 4) << 4);
            LDSM4(a[mi][0], a[mi][1], a[mi][2], a[mi][3], sA + SWZ(off));
        }
        uint32_t b[8][2];
#pragma unroll
        for (int nj = 0; nj < 4; nj++) {
            int nrow = wn * 64 + nj * 16 + (lane & 7) + ((lane & 16) >> 1);
            uint32_t off = nrow * 128 + ks * 32 + (((lane >> 3) & 1) << 4);
            uint32_t r0, r1, r2, r3;
            LDSM4(r0, r1, r2, r3, sB + SWZ(off));
            b[2 * nj][0] = r0;     b[2 * nj][1] = r1;
            b[2 * nj + 1][0] = r2; b[2 * nj + 1][1] = r3;
        }
#pragma unroll
        for (int mi = 0; mi < 4; mi++)
#pragma unroll
            for (int ni = 0; ni < 8; ni++)
                MMA16816(acc[mi][ni], a[mi], b[ni]);
    }
}

// ---------------- shared mainloop (single barrier per chunk) ----------------
// WAR safety: at iteration c, the top __syncthreads is reached by every thread
// only after it finished compute(c-1). The prefetch at iteration c targets
// stage (c+2)%3 == (c-1)%3, whose last reader was compute(c-1) -> covered.
__device__ __forceinline__ void gemm_mainloop(float (&acc)[4][8][4],
                                              const __nv_bfloat16* Ab,
                                              const __nv_bfloat16* Bb,
                                              int K, int nch, uint32_t sb,
                                              int row0, int col0,
                                              int tid, int wm, int wn, int lane) {
    load_chunk(Ab, Bb, K, 0,      0, sb, row0, col0, tid); CP_COMMIT();
    load_chunk(Ab, Bb, K, BK,     1, sb, row0, col0, tid); CP_COMMIT();

    for (int c = 0; c < nch; c++) {
        const int st = c % NST;
        if (c + 1 < nch) CP_WAIT(1); else CP_WAIT(0);
        __syncthreads();

        const int p = c + 2;
        if (p < nch) {
            load_chunk(Ab, Bb, K, p * BK, p % NST, sb, row0, col0, tid);
            CP_COMMIT();
        }
        uint32_t sA = sb + st * STAGE_B;
        uint32_t sB = sA + BM * 128;
        compute_chunk(acc, sA, sB, wm, wn, lane);
    }
}

// ---------------- phase S: student GEMM ----------------
__global__ void __launch_bounds__(256, 1)
gemm_s_kernel() {
    extern __shared__ __align__(1024) char smem[];
    uint32_t sb = smem_u32(smem);
    const int tid = threadIdx.x, wid = tid >> 5, lane = tid & 31;
    const int wm = wid & 1, wn = wid >> 1;
    const int mt = blockIdx.x, nt = blockIdx.y;
    const int row0 = mt * BM, col0 = nt * BN;
    const int ctaLin = nt * 32 + mt;

    float acc[4][8][4];
#pragma unroll
    for (int i = 0; i < 4; i++)
#pragma unroll
        for (int j = 0; j < 8; j++)
#pragma unroll
            for (int k = 0; k < 4; k++) acc[i][j][k] = 0.f;

    gemm_mainloop(acc, g_sin_bf, g_sw_bf, KS, NCH_S, sb, row0, col0, tid, wm, wn, lane);

    // ---- store S fragments to scratch (reg-layout, coalesced uint4) ----
    {
        size_t base = (size_t)ctaLin * 4096 + tid;   // uint4 units, stride 256
#pragma unroll
        for (int mi = 0; mi < 4; mi++) {
#pragma unroll
            for (int nj = 0; nj < 4; nj++) {         // two ni per uint4
                uint32_t u[4];
#pragma unroll
                for (int q = 0; q < 2; q++) {
                    int ni = nj * 2 + q;
                    __nv_bfloat162 p0 = __float22bfloat162_rn(
                        make_float2(acc[mi][ni][0], acc[mi][ni][1]));
                    __nv_bfloat162 p1 = __float22bfloat162_rn(
                        make_float2(acc[mi][ni][2], acc[mi][ni][3]));
                    u[2 * q]     = *reinterpret_cast<uint32_t*>(&p0);
                    u[2 * q + 1] = *reinterpret_cast<uint32_t*>(&p1);
                }
                g_slog[base + (size_t)(mi * 4 + nj) * 256] =
                    make_uint4(u[0], u[1], u[2], u[3]);
            }
        }
    }

    // ---- per-row partials (m, z, ssq) over this warp's 64 cols ----
#pragma unroll
    for (int mi = 0; mi < 4; mi++) {
#pragma unroll
        for (int h = 0; h < 2; h++) {
            float s[16];
#pragma unroll
            for (int ni = 0; ni < 8; ni++) {
                s[2 * ni]     = acc[mi][ni][h * 2];
                s[2 * ni + 1] = acc[mi][ni][h * 2 + 1];
            }
            float m = s[0];
#pragma unroll
            for (int j = 1; j < 16; j++) m = fmaxf(m, s[j]);
            float z = 0.f, ssq = 0.f;
#pragma unroll
            for (int j = 0; j < 16; j++) {
                z += __expf(s[j] - m);
                ssq = fmaf(s[j], s[j], ssq);
            }
#pragma unroll
            for (int off = 1; off < 4; off <<= 1) {
                float om = __shfl_xor_sync(0xffffffffu, m, off);
                float oz = __shfl_xor_sync(0xffffffffu, z, off);
                float os = __shfl_xor_sync(0xffffffffu, ssq, off);
                float nm = fmaxf(m, om);
                z = z * __expf(m - nm) + oz * __expf(om - nm);
                m = nm;
                ssq += os;
            }
            if ((lane & 3) == 0) {
                int row = row0 + wm * 64 + mi * 16 + h * 8 + (lane >> 2);
                size_t idx = (size_t)row * NPAD + nt * 4 + wn;
                g_m[idx] = m; g_z[idx] = z; g_ss[idx] = ssq;
            }
        }
    }
}

// ---------------- phase T: teacher GEMM + dot/tsq ----------------
__global__ void __launch_bounds__(256, 1)
gemm_t_kernel() {
    extern __shared__ __align__(1024) char smem[];
    uint32_t sb = smem_u32(smem);
    const int tid = threadIdx.x, wid = tid >> 5, lane = tid & 31;
    const int wm = wid & 1, wn = wid >> 1;
    const int mt = blockIdx.x, nt = blockIdx.y;
    const int row0 = mt * BM, col0 = nt * BN;
    const int ctaLin = nt * 32 + mt;

    float acc[4][8][4];
#pragma unroll
    for (int i = 0; i < 4; i++)
#pragma unroll
        for (int j = 0; j < 8; j++)
#pragma unroll
            for (int k = 0; k < 4; k++) acc[i][j][k] = 0.f;

    gemm_mainloop(acc, g_tin_bf, g_tw_bf, KT, NCH_T, sb, row0, col0, tid, wm, wn, lane);

    // ---- dot / tsq against reloaded S fragments ----
    size_t base = (size_t)ctaLin * 4096 + tid;
#pragma unroll
    for (int mi = 0; mi < 4; mi++) {
        uint32_t su[16];
#pragma unroll
        for (int nj = 0; nj < 4; nj++) {
            uint4 v = g_slog[base + (size_t)(mi * 4 + nj) * 256];
            su[4 * nj] = v.x; su[4 * nj + 1] = v.y;
            su[4 * nj + 2] = v.z; su[4 * nj + 3] = v.w;
        }
#pragma unroll
        for (int h = 0; h < 2; h++) {
            float d = 0.f, tsq = 0.f;
#pragma unroll
            for (int ni = 0; ni < 8; ni++) {
                uint32_t u = su[ni * 2 + h];          // regs (2h, 2h+1) of (mi,ni)
                float s0 = __uint_as_float(u << 16);
                float s1 = __uint_as_float(u & 0xffff0000u);
                float t0 = acc[mi][ni][h * 2];
                float t1 = acc[mi][ni][h * 2 + 1];
                d = fmaf(s0, t0, d); d = fmaf(s1, t1, d);
                tsq = fmaf(t0, t0, tsq); tsq = fmaf(t1, t1, tsq);
            }
#pragma unroll
            for (int off = 1; off < 4; off <<= 1) {
                d   += __shfl_xor_sync(0xffffffffu, d, off);
                tsq += __shfl_xor_sync(0xffffffffu, tsq, off);
            }
            if ((lane & 3) == 0) {
                int row = row0 + wm * 64 + mi * 16 + h * 8 + (lane >> 2);
                size_t idx = (size_t)row * NPAD + nt * 4 + wn;
                g_d[idx] = d; g_tt[idx] = tsq;
            }
        }
    }
}

// ---------------- K2: per-row combine + exact target logit ----------------
__global__ void combine_kernel(const int* __restrict__ tgt,
                               const float* __restrict__ s_in,
                               const float* __restrict__ s_w)
{
    int gw = (blockIdx.x * blockDim.x + threadIdx.x) >> 5;
    int lane = threadIdx.x & 31;
    if (gw >= BT) return;
    const int row = gw;

    float m = -FLT_MAX, z = 0.f, d = 0.f, ssq = 0.f, tsq = 0.f;
    for (int n = lane; n < NT4; n += 32) {
        size_t idx = (size_t)row * NPAD + n;
        float om = g_m[idx], oz = g_z[idx];
        float nm = fmaxf(m, om);
        z = z * __expf(m - nm) + oz * __expf(om - nm);
        m = nm;
        d += g_d[idx]; ssq += g_ss[idx]; tsq += g_tt[idx];
    }
#pragma unroll
    for (int off = 16; off > 0; off >>= 1) {
        float om = __shfl_xor_sync(0xffffffffu, m, off);
        float oz = __shfl_xor_sync(0xffffffffu, z, off);
        float od = __shfl_xor_sync(0xffffffffu, d, off);
        float os = __shfl_xor_sync(0xffffffffu, ssq, off);
        float ot = __shfl_xor_sync(0xffffffffu, tsq, off);
        float nm = fmaxf(m, om);
        z = z * __expf(m - nm) + oz * __expf(om - nm);
        m = nm;
        d += od; ssq += os; tsq += ot;
    }

    bool is64 = (tgt[1] == -1);            // int64 layout: high word of -100
    int t = is64 ? tgt[2 * row] : tgt[row];

    float ce = 0.f;
    if (t >= 0) {
        float p = 0.f;
        const float* a = s_in + (size_t)row * KS;
        const float* w = s_w + (size_t)t * KS;
        for (int k = lane * 4; k < KS; k += 128) {
            float4 va = *reinterpret_cast<const float4*>(&a[k]);
            float4 vw = *reinterpret_cast<const float4*>(&w[k]);
            p += va.x * vw.x + va.y * vw.y + va.z * vw.z + va.w * vw.w;
        }
#pragma unroll
        for (int off = 16; off > 0; off >>= 1)
            p += __shfl_xor_sync(0xffffffffu, p, off);
        ce = (m + __logf(z)) - p;
    }
    float cs = d / (fmaxf(sqrtf(ssq), 1e-12f) * fmaxf(sqrtf(tsq), 1e-12f));
    if (lane == 0) { g_row[2 * row] = ce; g_row[2 * row + 1] = cs; }
}

// ---------------- K3: final reduction ----------------
__global__ void finalize_kernel(float* __restrict__ out) {
    __shared__ float sce[256], scs[256];
    int tid = threadIdx.x;
    float ce = 0.f, cs = 0.f;
    for (int r = tid; r < BT; r += 256) {
        ce += g_row[2 * r];
        cs += 1.0f - g_row[2 * r + 1];
    }
    sce[tid] = ce; scs[tid] = cs;
    __syncthreads();
    for (int s = 128; s > 0; s >>= 1) {
        if (tid < s) { sce[tid] += sce[tid + s]; scs[tid] += scs[tid + s]; }
        __syncthreads();
    }
    if (tid == 0)
        out[0] = 0.5f * (sce[0] / (float)BT) + 0.25f * (scs[0] / (float)BT);
}

// ---------------- launch ----------------
extern "C" void kernel_launch(void* const* d_in, const int* in_sizes, int n_in,
                              void* d_out, int out_size)
{
    const float* s_in = (const float*)d_in[0];
    const float* t_in = (const float*)d_in[1];
    const float* s_w  = (const float*)d_in[2];
    const float* t_w  = (const float*)d_in[3];
    const int*   tgt  = (const int*)d_in[4];
    float* out = (float*)d_out;

    cudaFuncSetAttribute(gemm_s_kernel,
                         cudaFuncAttributeMaxDynamicSharedMemorySize, SMEM_BYTES);
    cudaFuncSetAttribute(gemm_t_kernel,
                         cudaFuncAttributeMaxDynamicSharedMemorySize, SMEM_BYTES);

    cvt_all_kernel<<<8192, 256>>>(s_in, t_in, s_w, t_w);

    dim3 grid(BT / BM, NT);
    gemm_s_kernel<<<grid, 256, SMEM_BYTES>>>();
    gemm_t_kernel<<<grid, 256, SMEM_BYTES>>>();

    combine_kernel<<<(BT * 32) / 256, 256>>>(tgt, s_in, s_w);
    finalize_kernel<<<1, 256>>>(out);
}

// round 8
// speedup vs baseline: 2.1860x; 1.0406x over previous
#include <cuda_runtime.h>
#include <cuda_bf16.h>
#include <math.h>
#include <float.h>
#include <stdint.h>

// ---------------- problem constants ----------------
#define BT   4096
#define KS   2048
#define KT   4096
#define VOC  32000
// ---------------- tiling ----------------
#define BM   128
#define BN   256
#define BK   128           // k-chunk (bf16 elems) = 2 x 128B subtiles per row
#define NT   125           // 32000/256 vocab tiles
#define NT4  500           // NT * 4 warp_n slices
#define NPAD 1024
#define NCH_S (KS/BK)      // 16
#define NCH_T (KT/BK)      // 32
#define NST  2
#define STAGE_B (BM*256 + BN*256)      // 96 KB
#define SMEM_BYTES (NST * STAGE_B)     // 192 KB
#define NCTA (32 * NT)                 // 4000

// ---------------- static device scratch ----------------
__device__ __nv_bfloat16 g_sin_bf[(size_t)BT * KS];
__device__ __nv_bfloat16 g_tin_bf[(size_t)BT * KT];
__device__ __nv_bfloat16 g_sw_bf [(size_t)VOC * KS];
__device__ __nv_bfloat16 g_tw_bf [(size_t)VOC * KT];

__device__ uint4 g_slog[(size_t)NCTA * 256 * 16];   // 262 MB: S fragments, reg-layout

__device__ float g_m [(size_t)BT * NPAD];
__device__ float g_z [(size_t)BT * NPAD];
__device__ float g_d [(size_t)BT * NPAD];
__device__ float g_ss[(size_t)BT * NPAD];
__device__ float g_tt[(size_t)BT * NPAD];
__device__ float g_row[BT * 2];

// ---------------- PTX helpers ----------------
__device__ __forceinline__ uint32_t smem_u32(const void* p) {
    uint32_t a;
    asm("{ .reg .u64 t; cvta.to.shared.u64 t, %1; cvt.u32.u64 %0, t; }" : "=r"(a) : "l"(p));
    return a;
}
#define SWZ(o) ((o) ^ (((o) >> 3) & 0x70))

#define CP16(dst, src) \
    asm volatile("cp.async.cg.shared.global [%0], [%1], 16;" :: "r"(dst), "l"(src) : "memory")
#define CP_COMMIT() asm volatile("cp.async.commit_group;" ::: "memory")
#define CP_WAIT(n)  asm volatile("cp.async.wait_group %0;" :: "n"(n) : "memory")

#define LDSM4(r0, r1, r2, r3, a) \
    asm volatile("ldmatrix.sync.aligned.m8n8.x4.shared.b16 {%0,%1,%2,%3}, [%4];" \
        : "=r"(r0), "=r"(r1), "=r"(r2), "=r"(r3) : "r"(a))

#define MMA16816(d, a, b) \
    asm volatile("mma.sync.aligned.m16n8k16.row.col.f32.bf16.bf16.f32 " \
        "{%0,%1,%2,%3}, {%4,%5,%6,%7}, {%8,%9}, {%0,%1,%2,%3};" \
        : "+f"((d)[0]), "+f"((d)[1]), "+f"((d)[2]), "+f"((d)[3]) \
        : "r"((a)[0]), "r"((a)[1]), "r"((a)[2]), "r"((a)[3]), \
          "r"((b)[0]), "r"((b)[1]))

// ---------------- fused fp32 -> bf16 conversion ----------------
#define N_SIN ((size_t)BT * KS)
#define N_TIN ((size_t)BT * KT)
#define N_SW  ((size_t)VOC * KS)
#define N_TW  ((size_t)VOC * KT)
#define N_TOT (N_SIN + N_TIN + N_SW + N_TW)

__global__ void cvt_all_kernel(const float* __restrict__ s_in,
                               const float* __restrict__ t_in,
                               const float* __restrict__ s_w,
                               const float* __restrict__ t_w) {
    size_t i = ((size_t)blockIdx.x * blockDim.x + threadIdx.x) * 4;
    size_t stride = (size_t)gridDim.x * blockDim.x * 4;
    for (; i < N_TOT; i += stride) {
        const float* src; __nv_bfloat16* dst; size_t off;
        if (i < N_SIN)                    { src = s_in; dst = g_sin_bf; off = i; }
        else if (i < N_SIN + N_TIN)       { src = t_in; dst = g_tin_bf; off = i - N_SIN; }
        else if (i < N_SIN + N_TIN + N_SW){ src = s_w;  dst = g_sw_bf;  off = i - N_SIN - N_TIN; }
        else                              { src = t_w;  dst = g_tw_bf;  off = i - N_SIN - N_TIN - N_SW; }
        float4 v = *reinterpret_cast<const float4*>(src + off);
        __nv_bfloat162 a = __float22bfloat162_rn(make_float2(v.x, v.y));
        __nv_bfloat162 b = __float22bfloat162_rn(make_float2(v.z, v.w));
        uint2 o;
        o.x = *reinterpret_cast<uint32_t*>(&a);
        o.y = *reinterpret_cast<uint32_t*>(&b);
        *reinterpret_cast<uint2*>(dst + off) = o;
    }
}

// ---------------- chunk loader: BK=128 as two 128B-row subtiles ----------------
// Stage layout: A sub0 [128x128B] @0, A sub1 @16KB, B sub0 [256x128B] @32KB, B sub1 @64KB.
__device__ __forceinline__ void load_chunk(const __nv_bfloat16* __restrict__ Ab,
                                           const __nv_bfloat16* __restrict__ Bb,
                                           int K, int k0, int st, uint32_t sb,
                                           int row0, int col0, int tid) {
    uint32_t sA = sb + st * STAGE_B;
    uint32_t sB = sA + BM * 256;
#pragma unroll
    for (int sub = 0; sub < 2; sub++) {
        int ke = k0 + sub * 64;
        uint32_t aBase = sA + sub * (BM * 128);
        uint32_t bBase = sB + sub * (BN * 128);
#pragma unroll
        for (int i = 0; i < 4; i++) {              // A: 128 rows x 128B
            int ls = tid + i * 256;
            int row = ls >> 3, cb = (ls & 7) * 16;
            const char* g = (const char*)(Ab + (size_t)(row0 + row) * K + ke) + cb;
            CP16(aBase + SWZ(ls * 16), g);
        }
#pragma unroll
        for (int i = 0; i < 8; i++) {              // B: 256 rows x 128B
            int ls = tid + i * 256;
            int row = ls >> 3, cb = (ls & 7) * 16;
            const char* g = (const char*)(Bb + (size_t)(col0 + row) * K + ke) + cb;
            CP16(bBase + SWZ(ls * 16), g);
        }
    }
}

// ---------------- one BK=128 chunk of MMAs: warp tile 64x64 ----------------
__device__ __forceinline__ void compute_chunk(float (&acc)[4][8][4],
                                              uint32_t sA, uint32_t sB,
                                              int wm, int wn, int lane) {
#pragma unroll
    for (int ks = 0; ks < 8; ks++) {
        const int sub = ks >> 2, ksl = ks & 3;
        uint32_t aBase = sA + sub * (BM * 128);
        uint32_t bBase = sB + sub * (BN * 128);
        uint32_t a[4][4];
#pragma unroll
        for (int mi = 0; mi < 4; mi++) {
            int row = wm * 64 + mi * 16 + (lane & 15);
            uint32_t off = row * 128 + ksl * 32 + ((lane >> 4) << 4);
            LDSM4(a[mi][0], a[mi][1], a[mi][2], a[mi][3], aBase + SWZ(off));
        }
        uint32_t b[8][2];
#pragma unroll
        for (int nj = 0; nj < 4; nj++) {
            int nrow = wn * 64 + nj * 16 + (lane & 7) + ((lane & 16) >> 1);
            uint32_t off = nrow * 128 + ksl * 32 + (((lane >> 3) & 1) << 4);
            uint32_t r0, r1, r2, r3;
            LDSM4(r0, r1, r2, r3, bBase + SWZ(off));
            b[2 * nj][0] = r0;     b[2 * nj][1] = r1;
            b[2 * nj + 1][0] = r2; b[2 * nj + 1][1] = r3;
        }
#pragma unroll
        for (int mi = 0; mi < 4; mi++)
#pragma unroll
            for (int ni = 0; ni < 8; ni++)
                MMA16816(acc[mi][ni], a[mi], b[ni]);
    }
}

// ---------------- mainloop: 2-stage ring, lag-1 prefetch, 1 barrier/chunk ----
// WAR safety: prefetch at iter c writes stage st^1 = stage of chunk c-1, whose
// compute finished before every thread reached this iteration's barrier.
__device__ __forceinline__ void gemm_mainloop(float (&acc)[4][8][4],
                                              const __nv_bfloat16* Ab,
                                              const __nv_bfloat16* Bb,
                                              int K, int nch, uint32_t sb,
                                              int row0, int col0,
                                              int tid, int wm, int wn, int lane) {
    load_chunk(Ab, Bb, K, 0, 0, sb, row0, col0, tid); CP_COMMIT();

    for (int c = 0; c < nch; c++) {
        const int st = c & 1;
        CP_WAIT(0);
        __syncthreads();

        if (c + 1 < nch) {
            load_chunk(Ab, Bb, K, (c + 1) * BK, st ^ 1, sb, row0, col0, tid);
            CP_COMMIT();
        }
        uint32_t sA = sb + st * STAGE_B;
        uint32_t sB = sA + BM * 256;
        compute_chunk(acc, sA, sB, wm, wn, lane);
    }
}

// ---------------- phase S: student GEMM ----------------
__global__ void __launch_bounds__(256, 1)
gemm_s_kernel() {
    extern __shared__ __align__(1024) char smem[];
    uint32_t sb = smem_u32(smem);
    const int tid = threadIdx.x, wid = tid >> 5, lane = tid & 31;
    const int wm = wid & 1, wn = wid >> 1;
    const int mt = blockIdx.x, nt = blockIdx.y;
    const int row0 = mt * BM, col0 = nt * BN;
    const int ctaLin = nt * 32 + mt;

    float acc[4][8][4];
#pragma unroll
    for (int i = 0; i < 4; i++)
#pragma unroll
        for (int j = 0; j < 8; j++)
#pragma unroll
            for (int k = 0; k < 4; k++) acc[i][j][k] = 0.f;

    gemm_mainloop(acc, g_sin_bf, g_sw_bf, KS, NCH_S, sb, row0, col0, tid, wm, wn, lane);

    // ---- store S fragments to scratch (reg-layout, coalesced uint4) ----
    {
        size_t base = (size_t)ctaLin * 4096 + tid;   // uint4 units, stride 256
#pragma unroll
        for (int mi = 0; mi < 4; mi++) {
#pragma unroll
            for (int nj = 0; nj < 4; nj++) {         // two ni per uint4
                uint32_t u[4];
#pragma unroll
                for (int q = 0; q < 2; q++) {
                    int ni = nj * 2 + q;
                    __nv_bfloat162 p0 = __float22bfloat162_rn(
                        make_float2(acc[mi][ni][0], acc[mi][ni][1]));
                    __nv_bfloat162 p1 = __float22bfloat162_rn(
                        make_float2(acc[mi][ni][2], acc[mi][ni][3]));
                    u[2 * q]     = *reinterpret_cast<uint32_t*>(&p0);
                    u[2 * q + 1] = *reinterpret_cast<uint32_t*>(&p1);
                }
                g_slog[base + (size_t)(mi * 4 + nj) * 256] =
                    make_uint4(u[0], u[1], u[2], u[3]);
            }
        }
    }

    // ---- per-row partials (m, z, ssq) over this warp's 64 cols ----
#pragma unroll
    for (int mi = 0; mi < 4; mi++) {
#pragma unroll
        for (int h = 0; h < 2; h++) {
            float s[16];
#pragma unroll
            for (int ni = 0; ni < 8; ni++) {
                s[2 * ni]     = acc[mi][ni][h * 2];
                s[2 * ni + 1] = acc[mi][ni][h * 2 + 1];
            }
            float m = s[0];
#pragma unroll
            for (int j = 1; j < 16; j++) m = fmaxf(m, s[j]);
            float z = 0.f, ssq = 0.f;
#pragma unroll
            for (int j = 0; j < 16; j++) {
                z += __expf(s[j] - m);
                ssq = fmaf(s[j], s[j], ssq);
            }
#pragma unroll
            for (int off = 1; off < 4; off <<= 1) {
                float om = __shfl_xor_sync(0xffffffffu, m, off);
                float oz = __shfl_xor_sync(0xffffffffu, z, off);
                float os = __shfl_xor_sync(0xffffffffu, ssq, off);
                float nm = fmaxf(m, om);
                z = z * __expf(m - nm) + oz * __expf(om - nm);
                m = nm;
                ssq += os;
            }
            if ((lane & 3) == 0) {
                int row = row0 + wm * 64 + mi * 16 + h * 8 + (lane >> 2);
                size_t idx = (size_t)row * NPAD + nt * 4 + wn;
                g_m[idx] = m; g_z[idx] = z; g_ss[idx] = ssq;
            }
        }
    }
}

// ---------------- phase T: teacher GEMM + dot/tsq ----------------
__global__ void __launch_bounds__(256, 1)
gemm_t_kernel() {
    extern __shared__ __align__(1024) char smem[];
    uint32_t sb = smem_u32(smem);
    const int tid = threadIdx.x, wid = tid >> 5, lane = tid & 31;
    const int wm = wid & 1, wn = wid >> 1;
    const int mt = blockIdx.x, nt = blockIdx.y;
    const int row0 = mt * BM, col0 = nt * BN;
    const int ctaLin = nt * 32 + mt;

    float acc[4][8][4];
#pragma unroll
    for (int i = 0; i < 4; i++)
#pragma unroll
        for (int j = 0; j < 8; j++)
#pragma unroll
            for (int k = 0; k < 4; k++) acc[i][j][k] = 0.f;

    gemm_mainloop(acc, g_tin_bf, g_tw_bf, KT, NCH_T, sb, row0, col0, tid, wm, wn, lane);

    // ---- dot / tsq against reloaded S fragments ----
    size_t base = (size_t)ctaLin * 4096 + tid;
#pragma unroll
    for (int mi = 0; mi < 4; mi++) {
        uint32_t su[16];
#pragma unroll
        for (int nj = 0; nj < 4; nj++) {
            uint4 v = g_slog[base + (size_t)(mi * 4 + nj) * 256];
            su[4 * nj] = v.x; su[4 * nj + 1] = v.y;
            su[4 * nj + 2] = v.z; su[4 * nj + 3] = v.w;
        }
#pragma unroll
        for (int h = 0; h < 2; h++) {
            float d = 0.f, tsq = 0.f;
#pragma unroll
            for (int ni = 0; ni < 8; ni++) {
                uint32_t u = su[ni * 2 + h];          // regs (2h, 2h+1) of (mi,ni)
                float s0 = __uint_as_float(u << 16);
                float s1 = __uint_as_float(u & 0xffff0000u);
                float t0 = acc[mi][ni][h * 2];
                float t1 = acc[mi][ni][h * 2 + 1];
                d = fmaf(s0, t0, d); d = fmaf(s1, t1, d);
                tsq = fmaf(t0, t0, tsq); tsq = fmaf(t1, t1, tsq);
            }
#pragma unroll
            for (int off = 1; off < 4; off <<= 1) {
                d   += __shfl_xor_sync(0xffffffffu, d, off);
                tsq += __shfl_xor_sync(0xffffffffu, tsq, off);
            }
            if ((lane & 3) == 0) {
                int row = row0 + wm * 64 + mi * 16 + h * 8 + (lane >> 2);
                size_t idx = (size_t)row * NPAD + nt * 4 + wn;
                g_d[idx] = d; g_tt[idx] = tsq;
            }
        }
    }
}

// ---------------- K2: per-row combine + exact target logit ----------------
__global__ void combine_kernel(const int* __restrict__ tgt,
                               const float* __restrict__ s_in,
                               const float* __restrict__ s_w)
{
    int gw = (blockIdx.x * blockDim.x + threadIdx.x) >> 5;
    int lane = threadIdx.x & 31;
    if (gw >= BT) return;
    const int row = gw;

    float m = -FLT_MAX, z = 0.f, d = 0.f, ssq = 0.f, tsq = 0.f;
    for (int n = lane; n < NT4; n += 32) {
        size_t idx = (size_t)row * NPAD + n;
        float om = g_m[idx], oz = g_z[idx];
        float nm = fmaxf(m, om);
        z = z * __expf(m - nm) + oz * __expf(om - nm);
        m = nm;
        d += g_d[idx]; ssq += g_ss[idx]; tsq += g_tt[idx];
    }
#pragma unroll
    for (int off = 16; off > 0; off >>= 1) {
        float om = __shfl_xor_sync(0xffffffffu, m, off);
        float oz = __shfl_xor_sync(0xffffffffu, z, off);
        float od = __shfl_xor_sync(0xffffffffu, d, off);
        float os = __shfl_xor_sync(0xffffffffu, ssq, off);
        float ot = __shfl_xor_sync(0xffffffffu, tsq, off);
        float nm = fmaxf(m, om);
        z = z * __expf(m - nm) + oz * __expf(om - nm);
        m = nm;
        d += od; ssq += os; tsq += ot;
    }

    bool is64 = (tgt[1] == -1);            // int64 layout: high word of -100
    int t = is64 ? tgt[2 * row] : tgt[row];

    float ce = 0.f;
    if (t >= 0) {
        float p = 0.f;
        const float* a = s_in + (size_t)row * KS;
        const float* w = s_w + (size_t)t * KS;
        for (int k = lane * 4; k < KS; k += 128) {
            float4 va = *reinterpret_cast<const float4*>(&a[k]);
            float4 vw = *reinterpret_cast<const float4*>(&w[k]);
            p += va.x * vw.x + va.y * vw.y + va.z * vw.z + va.w * vw.w;
        }
#pragma unroll
        for (int off = 16; off > 0; off >>= 1)
            p += __shfl_xor_sync(0xffffffffu, p, off);
        ce = (m + __logf(z)) - p;
    }
    float cs = d / (fmaxf(sqrtf(ssq), 1e-12f) * fmaxf(sqrtf(tsq), 1e-12f));
    if (lane == 0) { g_row[2 * row] = ce; g_row[2 * row + 1] = cs; }
}

// ---------------- K3: final reduction ----------------
__global__ void finalize_kernel(float* __restrict__ out) {
    __shared__ float sce[256], scs[256];
    int tid = threadIdx.x;
    float ce = 0.f, cs = 0.f;
    for (int r = tid; r < BT; r += 256) {
        ce += g_row[2 * r];
        cs += 1.0f - g_row[2 * r + 1];
    }
    sce[tid] = ce; scs[tid] = cs;
    __syncthreads();
    for (int s = 128; s > 0; s >>= 1) {
        if (tid < s) { sce[tid] += sce[tid + s]; scs[tid] += scs[tid + s]; }
        __syncthreads();
    }
    if (tid == 0)
        out[0] = 0.5f * (sce[0] / (float)BT) + 0.25f * (scs[0] / (float)BT);
}

// ---------------- launch ----------------
extern "C" void kernel_launch(void* const* d_in, const int* in_sizes, int n_in,
                              void* d_out, int out_size)
{
    const float* s_in = (const float*)d_in[0];
    const float* t_in = (const float*)d_in[1];
    const float* s_w  = (const float*)d_in[2];
    const float* t_w  = (const float*)d_in[3];
    const int*   tgt  = (const int*)d_in[4];
    float* out = (float*)d_out;

    cudaFuncSetAttribute(gemm_s_kernel,
                         cudaFuncAttributeMaxDynamicSharedMemorySize, SMEM_BYTES);
    cudaFuncSetAttribute(gemm_t_kernel,
                         cudaFuncAttributeMaxDynamicSharedMemorySize, SMEM_BYTES);

    cvt_all_kernel<<<8192, 256>>>(s_in, t_in, s_w, t_w);

    dim3 grid(BT / BM, NT);
    gemm_s_kernel<<<grid, 256, SMEM_BYTES>>>();
    gemm_t_kernel<<<grid, 256, SMEM_BYTES>>>();

    combine_kernel<<<(BT * 32) / 256, 256>>>(tgt, s_in, s_w);
    finalize_kernel<<<1, 256>>>(out);
}

// round 9
// speedup vs baseline: 2.1985x; 1.0057x over previous
#include <cuda_runtime.h>
#include <cuda_bf16.h>
#include <math.h>
#include <float.h>
#include <stdint.h>

// ---------------- problem constants ----------------
#define BT   4096
#define KS   2048
#define KT   4096
#define VOC  32000
// ---------------- tiling ----------------
#define BM   128
#define BN   256
#define BK   128           // k-chunk (bf16 elems) = 2 x 128B subtiles per row
#define NT   125           // 32000/256 vocab tiles
#define NT4  500           // NT * 4 warp_n slices
#define NPAD 1024
#define NCH_S (KS/BK)      // 16
#define NCH_T (KT/BK)      // 32
#define NST  2
#define STAGE_B (BM*256 + BN*256)      // 96 KB
#define SMEM_BYTES (NST * STAGE_B)     // 192 KB
#define NCTA (32 * NT)                 // 4000

// ---------------- static device scratch ----------------
__device__ __nv_bfloat16 g_sin_bf[(size_t)BT * KS];
__device__ __nv_bfloat16 g_tin_bf[(size_t)BT * KT];
__device__ __nv_bfloat16 g_sw_bf [(size_t)VOC * KS];
__device__ __nv_bfloat16 g_tw_bf [(size_t)VOC * KT];

__device__ uint4 g_slog[(size_t)NCTA * 256 * 16];   // 262 MB: S fragments, reg-layout

__device__ float g_m [(size_t)BT * NPAD];
__device__ float g_z [(size_t)BT * NPAD];
__device__ float g_d [(size_t)BT * NPAD];
__device__ float g_ss[(size_t)BT * NPAD];
__device__ float g_tt[(size_t)BT * NPAD];
__device__ float g_row[BT * 2];

// ---------------- PTX helpers ----------------
__device__ __forceinline__ uint32_t smem_u32(const void* p) {
    uint32_t a;
    asm("{ .reg .u64 t; cvta.to.shared.u64 t, %1; cvt.u32.u64 %0, t; }" : "=r"(a) : "l"(p));
    return a;
}
#define SWZ(o) ((o) ^ (((o) >> 3) & 0x70))

#define CP16(dst, src) \
    asm volatile("cp.async.cg.shared.global [%0], [%1], 16;" :: "r"(dst), "l"(src) : "memory")
#define CP_COMMIT() asm volatile("cp.async.commit_group;" ::: "memory")
#define CP_WAIT(n)  asm volatile("cp.async.wait_group %0;" :: "n"(n) : "memory")

#define LDSM4(r0, r1, r2, r3, a) \
    asm volatile("ldmatrix.sync.aligned.m8n8.x4.shared.b16 {%0,%1,%2,%3}, [%4];" \
        : "=r"(r0), "=r"(r1), "=r"(r2), "=r"(r3) : "r"(a))

#define MMA16816(d, a, b) \
    asm volatile("mma.sync.aligned.m16n8k16.row.col.f32.bf16.bf16.f32 " \
        "{%0,%1,%2,%3}, {%4,%5,%6,%7}, {%8,%9}, {%0,%1,%2,%3};" \
        : "+f"((d)[0]), "+f"((d)[1]), "+f"((d)[2]), "+f"((d)[3]) \
        : "r"((a)[0]), "r"((a)[1]), "r"((a)[2]), "r"((a)[3]), \
          "r"((b)[0]), "r"((b)[1]))

// ---------------- fused fp32 -> bf16 conversion ----------------
#define N_SIN ((size_t)BT * KS)
#define N_TIN ((size_t)BT * KT)
#define N_SW  ((size_t)VOC * KS)
#define N_TW  ((size_t)VOC * KT)
#define N_TOT (N_SIN + N_TIN + N_SW + N_TW)

__global__ void cvt_all_kernel(const float* __restrict__ s_in,
                               const float* __restrict__ t_in,
                               const float* __restrict__ s_w,
                               const float* __restrict__ t_w) {
    size_t i = ((size_t)blockIdx.x * blockDim.x + threadIdx.x) * 4;
    size_t stride = (size_t)gridDim.x * blockDim.x * 4;
    for (; i < N_TOT; i += stride) {
        const float* src; __nv_bfloat16* dst; size_t off;
        if (i < N_SIN)                    { src = s_in; dst = g_sin_bf; off = i; }
        else if (i < N_SIN + N_TIN)       { src = t_in; dst = g_tin_bf; off = i - N_SIN; }
        else if (i < N_SIN + N_TIN + N_SW){ src = s_w;  dst = g_sw_bf;  off = i - N_SIN - N_TIN; }
        else                              { src = t_w;  dst = g_tw_bf;  off = i - N_SIN - N_TIN - N_SW; }
        float4 v = *reinterpret_cast<const float4*>(src + off);
        __nv_bfloat162 a = __float22bfloat162_rn(make_float2(v.x, v.y));
        __nv_bfloat162 b = __float22bfloat162_rn(make_float2(v.z, v.w));
        uint2 o;
        o.x = *reinterpret_cast<uint32_t*>(&a);
        o.y = *reinterpret_cast<uint32_t*>(&b);
        *reinterpret_cast<uint2*>(dst + off) = o;
    }
}

// ---------------- chunk loader: BK=128 as two 128B-row subtiles ----------------
__device__ __forceinline__ void load_chunk(const __nv_bfloat16* __restrict__ Ab,
                                           const __nv_bfloat16* __restrict__ Bb,
                                           int K, int k0, int st, uint32_t sb,
                                           int row0, int col0, int tid) {
    uint32_t sA = sb + st * STAGE_B;
    uint32_t sB = sA + BM * 256;
#pragma unroll
    for (int sub = 0; sub < 2; sub++) {
        int ke = k0 + sub * 64;
        uint32_t aBase = sA + sub * (BM * 128);
        uint32_t bBase = sB + sub * (BN * 128);
#pragma unroll
        for (int i = 0; i < 4; i++) {              // A: 128 rows x 128B
            int ls = tid + i * 256;
            int row = ls >> 3, cb = (ls & 7) * 16;
            const char* g = (const char*)(Ab + (size_t)(row0 + row) * K + ke) + cb;
            CP16(aBase + SWZ(ls * 16), g);
        }
#pragma unroll
        for (int i = 0; i < 8; i++) {              // B: 256 rows x 128B
            int ls = tid + i * 256;
            int row = ls >> 3, cb = (ls & 7) * 16;
            const char* g = (const char*)(Bb + (size_t)(col0 + row) * K + ke) + cb;
            CP16(bBase + SWZ(ls * 16), g);
        }
    }
}

// ---------------- one BK=128 chunk of MMAs: warp tile 64x64 ----------------
__device__ __forceinline__ void compute_chunk(float (&acc)[4][8][4],
                                              uint32_t sA, uint32_t sB,
                                              int wm, int wn, int lane) {
#pragma unroll
    for (int ks = 0; ks < 8; ks++) {
        const int sub = ks >> 2, ksl = ks & 3;
        uint32_t aBase = sA + sub * (BM * 128);
        uint32_t bBase = sB + sub * (BN * 128);
        uint32_t a[4][4];
#pragma unroll
        for (int mi = 0; mi < 4; mi++) {
            int row = wm * 64 + mi * 16 + (lane & 15);
            uint32_t off = row * 128 + ksl * 32 + ((lane >> 4) << 4);
            LDSM4(a[mi][0], a[mi][1], a[mi][2], a[mi][3], aBase + SWZ(off));
        }
        uint32_t b[8][2];
#pragma unroll
        for (int nj = 0; nj < 4; nj++) {
            int nrow = wn * 64 + nj * 16 + (lane & 7) + ((lane & 16) >> 1);
            uint32_t off = nrow * 128 + ksl * 32 + (((lane >> 3) & 1) << 4);
            uint32_t r0, r1, r2, r3;
            LDSM4(r0, r1, r2, r3, bBase + SWZ(off));
            b[2 * nj][0] = r0;     b[2 * nj][1] = r1;
            b[2 * nj + 1][0] = r2; b[2 * nj + 1][1] = r3;
        }
#pragma unroll
        for (int mi = 0; mi < 4; mi++)
#pragma unroll
            for (int ni = 0; ni < 8; ni++)
                MMA16816(acc[mi][ni], a[mi], b[ni]);
    }
}

// ---------------- mainloop: 2-stage ring, lag-1 prefetch, 1 barrier/chunk ----
__device__ __forceinline__ void gemm_mainloop(float (&acc)[4][8][4],
                                              const __nv_bfloat16* Ab,
                                              const __nv_bfloat16* Bb,
                                              int K, int nch, uint32_t sb,
                                              int row0, int col0,
                                              int tid, int wm, int wn, int lane) {
    load_chunk(Ab, Bb, K, 0, 0, sb, row0, col0, tid); CP_COMMIT();

    for (int c = 0; c < nch; c++) {
        const int st = c & 1;
        CP_WAIT(0);
        __syncthreads();

        if (c + 1 < nch) {
            load_chunk(Ab, Bb, K, (c + 1) * BK, st ^ 1, sb, row0, col0, tid);
            CP_COMMIT();
        }
        uint32_t sA = sb + st * STAGE_B;
        uint32_t sB = sA + BM * 256;
        compute_chunk(acc, sA, sB, wm, wn, lane);
    }
}

// ---------------- merged S+T GEMM kernel ----------------
// 1D grid of 2*NCTA: bid < NCTA -> student phase, else teacher phase.
// T tile i (bid NCTA+i) depends on S tile i (bid i); with in-order CTA
// dispatch and <=148 CTAs in flight, S tile i retired long before bid
// NCTA+i launches (NCTA=4000 >> 148).
__global__ void __launch_bounds__(256, 1)
gemm_fused_kernel() {
    extern __shared__ __align__(1024) char smem[];
    uint32_t sb = smem_u32(smem);
    const int tid = threadIdx.x, wid = tid >> 5, lane = tid & 31;
    const int wm = wid & 1, wn = wid >> 1;
    const int bid = blockIdx.x;
    const int phase = (bid >= NCTA);
    const int lin = phase ? (bid - NCTA) : bid;
    const int mt = lin & 31, nt = lin >> 5;        // mt fast (matches 2D x-fast order)
    const int row0 = mt * BM, col0 = nt * BN;
    const int ctaLin = lin;                        // == nt*32+mt

    float acc[4][8][4];
#pragma unroll
    for (int i = 0; i < 4; i++)
#pragma unroll
        for (int j = 0; j < 8; j++)
#pragma unroll
            for (int k = 0; k < 4; k++) acc[i][j][k] = 0.f;

    if (!phase) {
        // ================= phase S =================
        gemm_mainloop(acc, g_sin_bf, g_sw_bf, KS, NCH_S, sb, row0, col0, tid, wm, wn, lane);

        // store S fragments to scratch (reg-layout, coalesced uint4)
        size_t base = (size_t)ctaLin * 4096 + tid;   // uint4 units, stride 256
#pragma unroll
        for (int mi = 0; mi < 4; mi++) {
#pragma unroll
            for (int nj = 0; nj < 4; nj++) {
                uint32_t u[4];
#pragma unroll
                for (int q = 0; q < 2; q++) {
                    int ni = nj * 2 + q;
                    __nv_bfloat162 p0 = __float22bfloat162_rn(
                        make_float2(acc[mi][ni][0], acc[mi][ni][1]));
                    __nv_bfloat162 p1 = __float22bfloat162_rn(
                        make_float2(acc[mi][ni][2], acc[mi][ni][3]));
                    u[2 * q]     = *reinterpret_cast<uint32_t*>(&p0);
                    u[2 * q + 1] = *reinterpret_cast<uint32_t*>(&p1);
                }
                g_slog[base + (size_t)(mi * 4 + nj) * 256] =
                    make_uint4(u[0], u[1], u[2], u[3]);
            }
        }

        // per-row partials (m, z, ssq) over this warp's 64 cols
#pragma unroll
        for (int mi = 0; mi < 4; mi++) {
#pragma unroll
            for (int h = 0; h < 2; h++) {
                float s[16];
#pragma unroll
                for (int ni = 0; ni < 8; ni++) {
                    s[2 * ni]     = acc[mi][ni][h * 2];
                    s[2 * ni + 1] = acc[mi][ni][h * 2 + 1];
                }
                float m = s[0];
#pragma unroll
                for (int j = 1; j < 16; j++) m = fmaxf(m, s[j]);
                float z = 0.f, ssq = 0.f;
#pragma unroll
                for (int j = 0; j < 16; j++) {
                    z += __expf(s[j] - m);
                    ssq = fmaf(s[j], s[j], ssq);
                }
#pragma unroll
                for (int off = 1; off < 4; off <<= 1) {
                    float om = __shfl_xor_sync(0xffffffffu, m, off);
                    float oz = __shfl_xor_sync(0xffffffffu, z, off);
                    float os = __shfl_xor_sync(0xffffffffu, ssq, off);
                    float nm = fmaxf(m, om);
                    z = z * __expf(m - nm) + oz * __expf(om - nm);
                    m = nm;
                    ssq += os;
                }
                if ((lane & 3) == 0) {
                    int row = row0 + wm * 64 + mi * 16 + h * 8 + (lane >> 2);
                    size_t idx = (size_t)row * NPAD + nt * 4 + wn;
                    g_m[idx] = m; g_z[idx] = z; g_ss[idx] = ssq;
                }
            }
        }
    } else {
        // ================= phase T =================
        gemm_mainloop(acc, g_tin_bf, g_tw_bf, KT, NCH_T, sb, row0, col0, tid, wm, wn, lane);

        // dot / tsq against reloaded S fragments
        size_t base = (size_t)ctaLin * 4096 + tid;
#pragma unroll
        for (int mi = 0; mi < 4; mi++) {
            uint32_t su[16];
#pragma unroll
            for (int nj = 0; nj < 4; nj++) {
                uint4 v = g_slog[base + (size_t)(mi * 4 + nj) * 256];
                su[4 * nj] = v.x; su[4 * nj + 1] = v.y;
                su[4 * nj + 2] = v.z; su[4 * nj + 3] = v.w;
            }
#pragma unroll
            for (int h = 0; h < 2; h++) {
                float d = 0.f, tsq = 0.f;
#pragma unroll
                for (int ni = 0; ni < 8; ni++) {
                    uint32_t u = su[ni * 2 + h];      // regs (2h, 2h+1) of (mi,ni)
                    float s0 = __uint_as_float(u << 16);
                    float s1 = __uint_as_float(u & 0xffff0000u);
                    float t0 = acc[mi][ni][h * 2];
                    float t1 = acc[mi][ni][h * 2 + 1];
                    d = fmaf(s0, t0, d); d = fmaf(s1, t1, d);
                    tsq = fmaf(t0, t0, tsq); tsq = fmaf(t1, t1, tsq);
                }
#pragma unroll
                for (int off = 1; off < 4; off <<= 1) {
                    d   += __shfl_xor_sync(0xffffffffu, d, off);
                    tsq += __shfl_xor_sync(0xffffffffu, tsq, off);
                }
                if ((lane & 3) == 0) {
                    int row = row0 + wm * 64 + mi * 16 + h * 8 + (lane >> 2);
                    size_t idx = (size_t)row * NPAD + nt * 4 + wn;
                    g_d[idx] = d; g_tt[idx] = tsq;
                }
            }
        }
    }
}

// ---------------- K2: per-row combine + exact target logit ----------------
__global__ void combine_kernel(const int* __restrict__ tgt,
                               const float* __restrict__ s_in,
                               const float* __restrict__ s_w)
{
    int gw = (blockIdx.x * blockDim.x + threadIdx.x) >> 5;
    int lane = threadIdx.x & 31;
    if (gw >= BT) return;
    const int row = gw;

    float m = -FLT_MAX, z = 0.f, d = 0.f, ssq = 0.f, tsq = 0.f;
    for (int n = lane; n < NT4; n += 32) {
        size_t idx = (size_t)row * NPAD + n;
        float om = g_m[idx], oz = g_z[idx];
        float nm = fmaxf(m, om);
        z = z * __expf(m - nm) + oz * __expf(om - nm);
        m = nm;
        d += g_d[idx]; ssq += g_ss[idx]; tsq += g_tt[idx];
    }
#pragma unroll
    for (int off = 16; off > 0; off >>= 1) {
        float om = __shfl_xor_sync(0xffffffffu, m, off);
        float oz = __shfl_xor_sync(0xffffffffu, z, off);
        float od = __shfl_xor_sync(0xffffffffu, d, off);
        float os = __shfl_xor_sync(0xffffffffu, ssq, off);
        float ot = __shfl_xor_sync(0xffffffffu, tsq, off);
        float nm = fmaxf(m, om);
        z = z * __expf(m - nm) + oz * __expf(om - nm);
        m = nm;
        d += od; ssq += os; tsq += ot;
    }

    bool is64 = (tgt[1] == -1);            // int64 layout: high word of -100
    int t = is64 ? tgt[2 * row] : tgt[row];

    float ce = 0.f;
    if (t >= 0) {
        float p = 0.f;
        const float* a = s_in + (size_t)row * KS;
        const float* w = s_w + (size_t)t * KS;
        for (int k = lane * 4; k < KS; k += 128) {
            float4 va = *reinterpret_cast<const float4*>(&a[k]);
            float4 vw = *reinterpret_cast<const float4*>(&w[k]);
            p += va.x * vw.x + va.y * vw.y + va.z * vw.z + va.w * vw.w;
        }
#pragma unroll
        for (int off = 16; off > 0; off >>= 1)
            p += __shfl_xor_sync(0xffffffffu, p, off);
        ce = (m + __logf(z)) - p;
    }
    float cs = d / (fmaxf(sqrtf(ssq), 1e-12f) * fmaxf(sqrtf(tsq), 1e-12f));
    if (lane == 0) { g_row[2 * row] = ce; g_row[2 * row + 1] = cs; }
}

// ---------------- K3: final reduction ----------------
__global__ void finalize_kernel(float* __restrict__ out) {
    __shared__ float sce[256], scs[256];
    int tid = threadIdx.x;
    float ce = 0.f, cs = 0.f;
    for (int r = tid; r < BT; r += 256) {
        ce += g_row[2 * r];
        cs += 1.0f - g_row[2 * r + 1];
    }
    sce[tid] = ce; scs[tid] = cs;
    __syncthreads();
    for (int s = 128; s > 0; s >>= 1) {
        if (tid < s) { sce[tid] += sce[tid + s]; scs[tid] += scs[tid + s]; }
        __syncthreads();
    }
    if (tid == 0)
        out[0] = 0.5f * (sce[0] / (float)BT) + 0.25f * (scs[0] / (float)BT);
}

// ---------------- launch ----------------
extern "C" void kernel_launch(void* const* d_in, const int* in_sizes, int n_in,
                              void* d_out, int out_size)
{
    const float* s_in = (const float*)d_in[0];
    const float* t_in = (const float*)d_in[1];
    const float* s_w  = (const float*)d_in[2];
    const float* t_w  = (const float*)d_in[3];
    const int*   tgt  = (const int*)d_in[4];
    float* out = (float*)d_out;

    cudaFuncSetAttribute(gemm_fused_kernel,
                         cudaFuncAttributeMaxDynamicSharedMemorySize, SMEM_BYTES);

    cvt_all_kernel<<<8192, 256>>>(s_in, t_in, s_w, t_w);

    gemm_fused_kernel<<<2 * NCTA, 256, SMEM_BYTES>>>();

    combine_kernel<<<(BT * 32) / 256, 256>>>(tgt, s_in, s_w);
    finalize_kernel<<<1, 256>>>(out);
}

// round 10
// speedup vs baseline: 2.3310x; 1.0603x over previous
#include <cuda_runtime.h>
#include <cuda_bf16.h>
#include <math.h>
#include <float.h>
#include <stdint.h>

// ---------------- problem constants ----------------
#define BT   4096
#define KS   2048
#define KT   4096
#define VOC  32000
// ---------------- tiling ----------------
#define BM   128
#define BN   256
#define BK   128           // k-chunk (bf16 elems) = 2 x 128B subtiles per row
#define NT   125           // 32000/256 vocab tiles
#define NT4  500           // NT * 4 warp_n slices
#define NPAD 1024
#define NCH_S (KS/BK)      // 16
#define NCH_T (KT/BK)      // 32
#define NST  2
#define STAGE_B (BM*256 + BN*256)      // 96 KB
#define SMEM_BYTES (NST * STAGE_B)     // 192 KB
#define NCTA (32 * NT)                 // 4000

// ---------------- static device scratch ----------------
__device__ __nv_bfloat16 g_sin_bf[(size_t)BT * KS];
__device__ __nv_bfloat16 g_tin_bf[(size_t)BT * KT];
__device__ __nv_bfloat16 g_sw_bf [(size_t)VOC * KS];
__device__ __nv_bfloat16 g_tw_bf [(size_t)VOC * KT];

__device__ uint4 g_slog[(size_t)NCTA * 256 * 16];   // 262 MB: S fragments, reg-layout

__device__ float g_m [(size_t)BT * NPAD];
__device__ float g_z [(size_t)BT * NPAD];
__device__ float g_d [(size_t)BT * NPAD];
__device__ float g_ss[(size_t)BT * NPAD];
__device__ float g_tt[(size_t)BT * NPAD];
__device__ float g_row[BT * 2];

// ---------------- PTX helpers ----------------
__device__ __forceinline__ uint32_t smem_u32(const void* p) {
    uint32_t a;
    asm("{ .reg .u64 t; cvta.to.shared.u64 t, %1; cvt.u32.u64 %0, t; }" : "=r"(a) : "l"(p));
    return a;
}
#define SWZ(o) ((o) ^ (((o) >> 3) & 0x70))

#define CP16(dst, src) \
    asm volatile("cp.async.cg.shared.global [%0], [%1], 16;" :: "r"(dst), "l"(src) : "memory")
#define CP_COMMIT() asm volatile("cp.async.commit_group;" ::: "memory")
#define CP_WAIT(n)  asm volatile("cp.async.wait_group %0;" :: "n"(n) : "memory")

#define LDSM4(r0, r1, r2, r3, a) \
    asm volatile("ldmatrix.sync.aligned.m8n8.x4.shared.b16 {%0,%1,%2,%3}, [%4];" \
        : "=r"(r0), "=r"(r1), "=r"(r2), "=r"(r3) : "r"(a))

#define MMA16816(d, a, b) \
    asm volatile("mma.sync.aligned.m16n8k16.row.col.f32.bf16.bf16.f32 " \
        "{%0,%1,%2,%3}, {%4,%5,%6,%7}, {%8,%9}, {%0,%1,%2,%3};" \
        : "+f"((d)[0]), "+f"((d)[1]), "+f"((d)[2]), "+f"((d)[3]) \
        : "r"((a)[0]), "r"((a)[1]), "r"((a)[2]), "r"((a)[3]), \
          "r"((b)[0]), "r"((b)[1]))

// ---------------- fused fp32 -> bf16 conversion ----------------
#define N_SIN ((size_t)BT * KS)
#define N_TIN ((size_t)BT * KT)
#define N_SW  ((size_t)VOC * KS)
#define N_TW  ((size_t)VOC * KT)
#define N_TOT (N_SIN + N_TIN + N_SW + N_TW)

__global__ void cvt_all_kernel(const float* __restrict__ s_in,
                               const float* __restrict__ t_in,
                               const float* __restrict__ s_w,
                               const float* __restrict__ t_w) {
    size_t i = ((size_t)blockIdx.x * blockDim.x + threadIdx.x) * 4;
    size_t stride = (size_t)gridDim.x * blockDim.x * 4;
    for (; i < N_TOT; i += stride) {
        const float* src; __nv_bfloat16* dst; size_t off;
        if (i < N_SIN)                    { src = s_in; dst = g_sin_bf; off = i; }
        else if (i < N_SIN + N_TIN)       { src = t_in; dst = g_tin_bf; off = i - N_SIN; }
        else if (i < N_SIN + N_TIN + N_SW){ src = s_w;  dst = g_sw_bf;  off = i - N_SIN - N_TIN; }
        else                              { src = t_w;  dst = g_tw_bf;  off = i - N_SIN - N_TIN - N_SW; }
        float4 v = *reinterpret_cast<const float4*>(src + off);
        __nv_bfloat162 a = __float22bfloat162_rn(make_float2(v.x, v.y));
        __nv_bfloat162 b = __float22bfloat162_rn(make_float2(v.z, v.w));
        uint2 o;
        o.x = *reinterpret_cast<uint32_t*>(&a);
        o.y = *reinterpret_cast<uint32_t*>(&b);
        *reinterpret_cast<uint2*>(dst + off) = o;
    }
}

// ---------------- bulk chunk loader (prologue only) ----------------
__device__ __forceinline__ void load_chunk(const __nv_bfloat16* __restrict__ Ab,
                                           const __nv_bfloat16* __restrict__ Bb,
                                           int K, int k0, int st, uint32_t sb,
                                           int row0, int col0, int tid) {
    uint32_t sA = sb + st * STAGE_B;
    uint32_t sB = sA + BM * 256;
#pragma unroll
    for (int sub = 0; sub < 2; sub++) {
        int ke = k0 + sub * 64;
        uint32_t aBase = sA + sub * (BM * 128);
        uint32_t bBase = sB + sub * (BN * 128);
#pragma unroll
        for (int i = 0; i < 4; i++) {
            int ls = tid + i * 256;
            int row = ls >> 3, cb = (ls & 7) * 16;
            const char* g = (const char*)(Ab + (size_t)(row0 + row) * K + ke) + cb;
            CP16(aBase + SWZ(ls * 16), g);
        }
#pragma unroll
        for (int i = 0; i < 8; i++) {
            int ls = tid + i * 256;
            int row = ls >> 3, cb = (ls & 7) * 16;
            const char* g = (const char*)(Bb + (size_t)(col0 + row) * K + ke) + cb;
            CP16(bBase + SWZ(ls * 16), g);
        }
    }
}

// ---------------- compute chunk + interleaved prefetch of next chunk --------
// 24 cp.asyncs for chunk (k0n) are issued 6-per-ks over ks=0..3, overlapping
// HMMA issue instead of serializing at the chunk boundary (LDGSTS rt=8/SMSP).
__device__ __forceinline__ void compute_chunk_pf(float (&acc)[4][8][4],
        uint32_t sA, uint32_t sB, int wm, int wn, int lane,
        bool pf, const __nv_bfloat16* __restrict__ Ab,
        const __nv_bfloat16* __restrict__ Bb, int K, int k0n,
        uint32_t pfA, uint32_t pfB, int row0, int col0, int tid) {
#pragma unroll
    for (int ks = 0; ks < 8; ks++) {
        const int sub = ks >> 2, ksl = ks & 3;
        uint32_t aBase = sA + sub * (BM * 128);
        uint32_t bBase = sB + sub * (BN * 128);
        uint32_t a[4][4];
#pragma unroll
        for (int mi = 0; mi < 4; mi++) {
            int row = wm * 64 + mi * 16 + (lane & 15);
            uint32_t off = row * 128 + ksl * 32 + ((lane >> 4) << 4);
            LDSM4(a[mi][0], a[mi][1], a[mi][2], a[mi][3], aBase + SWZ(off));
        }
        uint32_t b[8][2];
#pragma unroll
        for (int nj = 0; nj < 4; nj++) {
            int nrow = wn * 64 + nj * 16 + (lane & 7) + ((lane & 16) >> 1);
            uint32_t off = nrow * 128 + ksl * 32 + (((lane >> 3) & 1) << 4);
            uint32_t r0, r1, r2, r3;
            LDSM4(r0, r1, r2, r3, bBase + SWZ(off));
            b[2 * nj][0] = r0;     b[2 * nj][1] = r1;
            b[2 * nj + 1][0] = r2; b[2 * nj + 1][1] = r3;
        }

        // interleaved prefetch: flat load index j = ks*6+q in [0,24)
        if (pf && ks < 4) {
#pragma unroll
            for (int q = 0; q < 6; q++) {
                const int j = ks * 6 + q;
                const int psub = j / 12, r = j % 12;
                const int ke = k0n + psub * 64;
                if (r < 4) {               // A load r
                    int ls = tid + r * 256;
                    int row = ls >> 3, cb = (ls & 7) * 16;
                    const char* g = (const char*)(Ab + (size_t)(row0 + row) * K + ke) + cb;
                    CP16(pfA + psub * (BM * 128) + SWZ(ls * 16), g);
                } else {                   // B load r-4
                    int i = r - 4;
                    int ls = tid + i * 256;
                    int row = ls >> 3, cb = (ls & 7) * 16;
                    const char* g = (const char*)(Bb + (size_t)(col0 + row) * K + ke) + cb;
                    CP16(pfB + psub * (BN * 128) + SWZ(ls * 16), g);
                }
            }
        }

#pragma unroll
        for (int mi = 0; mi < 4; mi++)
#pragma unroll
            for (int ni = 0; ni < 8; ni++)
                MMA16816(acc[mi][ni], a[mi], b[ni]);
    }
    CP_COMMIT();   // one group per chunk (empty group when pf==false: harmless)
}

// ---------------- mainloop: 2-stage ring, prefetch folded into compute ------
__device__ __forceinline__ void gemm_mainloop(float (&acc)[4][8][4],
                                              const __nv_bfloat16* Ab,
                                              const __nv_bfloat16* Bb,
                                              int K, int nch, uint32_t sb,
                                              int row0, int col0,
                                              int tid, int wm, int wn, int lane) {
    load_chunk(Ab, Bb, K, 0, 0, sb, row0, col0, tid); CP_COMMIT();

    for (int c = 0; c < nch; c++) {
        const int st = c & 1;
        CP_WAIT(0);
        __syncthreads();   // chunk c visible to all; stage st^1 free (compute c-1 done)

        uint32_t sA = sb + st * STAGE_B;
        uint32_t sB = sA + BM * 256;
        uint32_t oA = sb + (st ^ 1) * STAGE_B;
        uint32_t oB = oA + BM * 256;
        compute_chunk_pf(acc, sA, sB, wm, wn, lane,
                         (c + 1 < nch), Ab, Bb, K, (c + 1) * BK,
                         oA, oB, row0, col0, tid);
    }
}

// ---------------- merged S+T GEMM kernel ----------------
// 1D grid of 2*NCTA: bid < NCTA -> student phase, else teacher phase.
// T tile i (bid NCTA+i) depends on S tile i (bid i); in-order dispatch with
// <=148 CTAs in flight guarantees S tile i retired long before bid NCTA+i.
__global__ void __launch_bounds__(256, 1)
gemm_fused_kernel() {
    extern __shared__ __align__(1024) char smem[];
    uint32_t sb = smem_u32(smem);
    const int tid = threadIdx.x, wid = tid >> 5, lane = tid & 31;
    const int wm = wid & 1, wn = wid >> 1;
    const int bid = blockIdx.x;
    const int phase = (bid >= NCTA);
    const int lin = phase ? (bid - NCTA) : bid;
    const int mt = lin & 31, nt = lin >> 5;
    const int row0 = mt * BM, col0 = nt * BN;
    const int ctaLin = lin;

    float acc[4][8][4];
#pragma unroll
    for (int i = 0; i < 4; i++)
#pragma unroll
        for (int j = 0; j < 8; j++)
#pragma unroll
            for (int k = 0; k < 4; k++) acc[i][j][k] = 0.f;

    if (!phase) {
        // ================= phase S =================
        gemm_mainloop(acc, g_sin_bf, g_sw_bf, KS, NCH_S, sb, row0, col0, tid, wm, wn, lane);

        size_t base = (size_t)ctaLin * 4096 + tid;
#pragma unroll
        for (int mi = 0; mi < 4; mi++) {
#pragma unroll
            for (int nj = 0; nj < 4; nj++) {
                uint32_t u[4];
#pragma unroll
                for (int q = 0; q < 2; q++) {
                    int ni = nj * 2 + q;
                    __nv_bfloat162 p0 = __float22bfloat162_rn(
                        make_float2(acc[mi][ni][0], acc[mi][ni][1]));
                    __nv_bfloat162 p1 = __float22bfloat162_rn(
                        make_float2(acc[mi][ni][2], acc[mi][ni][3]));
                    u[2 * q]     = *reinterpret_cast<uint32_t*>(&p0);
                    u[2 * q + 1] = *reinterpret_cast<uint32_t*>(&p1);
                }
                g_slog[base + (size_t)(mi * 4 + nj) * 256] =
                    make_uint4(u[0], u[1], u[2], u[3]);
            }
        }

#pragma unroll
        for (int mi = 0; mi < 4; mi++) {
#pragma unroll
            for (int h = 0; h < 2; h++) {
                float s[16];
#pragma unroll
                for (int ni = 0; ni < 8; ni++) {
                    s[2 * ni]     = acc[mi][ni][h * 2];
                    s[2 * ni + 1] = acc[mi][ni][h * 2 + 1];
                }
                float m = s[0];
#pragma unroll
                for (int j = 1; j < 16; j++) m = fmaxf(m, s[j]);
                float z = 0.f, ssq = 0.f;
#pragma unroll
                for (int j = 0; j < 16; j++) {
                    z += __expf(s[j] - m);
                    ssq = fmaf(s[j], s[j], ssq);
                }
#pragma unroll
                for (int off = 1; off < 4; off <<= 1) {
                    float om = __shfl_xor_sync(0xffffffffu, m, off);
                    float oz = __shfl_xor_sync(0xffffffffu, z, off);
                    float os = __shfl_xor_sync(0xffffffffu, ssq, off);
                    float nm = fmaxf(m, om);
                    z = z * __expf(m - nm) + oz * __expf(om - nm);
                    m = nm;
                    ssq += os;
                }
                if ((lane & 3) == 0) {
                    int row = row0 + wm * 64 + mi * 16 + h * 8 + (lane >> 2);
                    size_t idx = (size_t)row * NPAD + nt * 4 + wn;
                    g_m[idx] = m; g_z[idx] = z; g_ss[idx] = ssq;
                }
            }
        }
    } else {
        // ================= phase T =================
        gemm_mainloop(acc, g_tin_bf, g_tw_bf, KT, NCH_T, sb, row0, col0, tid, wm, wn, lane);

        size_t base = (size_t)ctaLin * 4096 + tid;
#pragma unroll
        for (int mi = 0; mi < 4; mi++) {
            uint32_t su[16];
#pragma unroll
            for (int nj = 0; nj < 4; nj++) {
                uint4 v = g_slog[base + (size_t)(mi * 4 + nj) * 256];
                su[4 * nj] = v.x; su[4 * nj + 1] = v.y;
                su[4 * nj + 2] = v.z; su[4 * nj + 3] = v.w;
            }
#pragma unroll
            for (int h = 0; h < 2; h++) {
                float d = 0.f, tsq = 0.f;
#pragma unroll
                for (int ni = 0; ni < 8; ni++) {
                    uint32_t u = su[ni * 2 + h];
                    float s0 = __uint_as_float(u << 16);
                    float s1 = __uint_as_float(u & 0xffff0000u);
                    float t0 = acc[mi][ni][h * 2];
                    float t1 = acc[mi][ni][h * 2 + 1];
                    d = fmaf(s0, t0, d); d = fmaf(s1, t1, d);
                    tsq = fmaf(t0, t0, tsq); tsq = fmaf(t1, t1, tsq);
                }
#pragma unroll
                for (int off = 1; off < 4; off <<= 1) {
                    d   += __shfl_xor_sync(0xffffffffu, d, off);
                    tsq += __shfl_xor_sync(0xffffffffu, tsq, off);
                }
                if ((lane & 3) == 0) {
                    int row = row0 + wm * 64 + mi * 16 + h * 8 + (lane >> 2);
                    size_t idx = (size_t)row * NPAD + nt * 4 + wn;
                    g_d[idx] = d; g_tt[idx] = tsq;
                }
            }
        }
    }
}

// ---------------- K2: per-row combine + exact target logit ----------------
__global__ void combine_kernel(const int* __restrict__ tgt,
                               const float* __restrict__ s_in,
                               const float* __restrict__ s_w)
{
    int gw = (blockIdx.x * blockDim.x + threadIdx.x) >> 5;
    int lane = threadIdx.x & 31;
    if (gw >= BT) return;
    const int row = gw;

    float m = -FLT_MAX, z = 0.f, d = 0.f, ssq = 0.f, tsq = 0.f;
    for (int n = lane; n < NT4; n += 32) {
        size_t idx = (size_t)row * NPAD + n;
        float om = g_m[idx], oz = g_z[idx];
        float nm = fmaxf(m, om);
        z = z * __expf(m - nm) + oz * __expf(om - nm);
        m = nm;
        d += g_d[idx]; ssq += g_ss[idx]; tsq += g_tt[idx];
    }
#pragma unroll
    for (int off = 16; off > 0; off >>= 1) {
        float om = __shfl_xor_sync(0xffffffffu, m, off);
        float oz = __shfl_xor_sync(0xffffffffu, z, off);
        float od = __shfl_xor_sync(0xffffffffu, d, off);
        float os = __shfl_xor_sync(0xffffffffu, ssq, off);
        float ot = __shfl_xor_sync(0xffffffffu, tsq, off);
        float nm = fmaxf(m, om);
        z = z * __expf(m - nm) + oz * __expf(om - nm);
        m = nm;
        d += od; ssq += os; tsq += ot;
    }

    bool is64 = (tgt[1] == -1);            // int64 layout: high word of -100
    int t = is64 ? tgt[2 * row] : tgt[row];

    float ce = 0.f;
    if (t >= 0) {
        float p = 0.f;
        const float* a = s_in + (size_t)row * KS;
        const float* w = s_w + (size_t)t * KS;
        for (int k = lane * 4; k < KS; k += 128) {
            float4 va = *reinterpret_cast<const float4*>(&a[k]);
            float4 vw = *reinterpret_cast<const float4*>(&w[k]);
            p += va.x * vw.x + va.y * vw.y + va.z * vw.z + va.w * vw.w;
        }
#pragma unroll
        for (int off = 16; off > 0; off >>= 1)
            p += __shfl_xor_sync(0xffffffffu, p, off);
        ce = (m + __logf(z)) - p;
    }
    float cs = d / (fmaxf(sqrtf(ssq), 1e-12f) * fmaxf(sqrtf(tsq), 1e-12f));
    if (lane == 0) { g_row[2 * row] = ce; g_row[2 * row + 1] = cs; }
}

// ---------------- K3: final reduction ----------------
__global__ void finalize_kernel(float* __restrict__ out) {
    __shared__ float sce[256], scs[256];
    int tid = threadIdx.x;
    float ce = 0.f, cs = 0.f;
    for (int r = tid; r < BT; r += 256) {
        ce += g_row[2 * r];
        cs += 1.0f - g_row[2 * r + 1];
    }
    sce[tid] = ce; scs[tid] = cs;
    __syncthreads();
    for (int s = 128; s > 0; s >>= 1) {
        if (tid < s) { sce[tid] += sce[tid + s]; scs[tid] += scs[tid + s]; }
        __syncthreads();
    }
    if (tid == 0)
        out[0] = 0.5f * (sce[0] / (float)BT) + 0.25f * (scs[0] / (float)BT);
}

// ---------------- launch ----------------
extern "C" void kernel_launch(void* const* d_in, const int* in_sizes, int n_in,
                              void* d_out, int out_size)
{
    const float* s_in = (const float*)d_in[0];
    const float* t_in = (const float*)d_in[1];
    const float* s_w  = (const float*)d_in[2];
    const float* t_w  = (const float*)d_in[3];
    const int*   tgt  = (const int*)d_in[4];
    float* out = (float*)d_out;

    cudaFuncSetAttribute(gemm_fused_kernel,
                         cudaFuncAttributeMaxDynamicSharedMemorySize, SMEM_BYTES);

    cvt_all_kernel<<<8192, 256>>>(s_in, t_in, s_w, t_w);

    gemm_fused_kernel<<<2 * NCTA, 256, SMEM_BYTES>>>();

    combine_kernel<<<(BT * 32) / 256, 256>>>(tgt, s_in, s_w);
    finalize_kernel<<<1, 256>>>(out);
}